// round 2
// baseline (speedup 1.0000x reference)
#include <cuda_runtime.h>
#include <cstddef>

// ---------------------------------------------------------------------------
// DSDModules: G=8 group conv stacks (512->128->64->32->18, 3x3 SAME, lrelu 0.1
// between, none on last) on concat(gar_feat, cond_feat), then cross-group
// softmax attention + K=6 deformable bilinear warps of gar_feat, masked sum.
// All fp32. Conv inner loops use packed fma.rn.f32x2 (2x fp32 throughput).
// ---------------------------------------------------------------------------

#define NG   8
#define NK   6
#define CF   256
#define HH   64
#define WW   64
#define NP   4096   // H*W

typedef unsigned long long ull;

// ---- scratch (static device allocation; no cudaMalloc anywhere) -----------
// offsets in floats
#define OFF_GART 0ull
#define OFF_WT1  1048576ull
#define OFF_WT2  5767168ull
#define OFF_WT3  6356992ull
#define OFF_WT4  6504448ull
#define OFF_HID1 6559744ull
#define OFF_HID2 10754048ull
#define OFF_HID3 12851200ull
#define OFF_OA   13899776ull
#define SCRATCH_FLOATS 14686208ull

__device__ float g_scratch[SCRATCH_FLOATS];

// ---- packed f32x2 helpers -------------------------------------------------
__device__ __forceinline__ ull fma2(ull a, ull b, ull c) {
    ull d;
    asm("fma.rn.f32x2 %0, %1, %2, %3;" : "=l"(d) : "l"(a), "l"(b), "l"(c));
    return d;
}
__device__ __forceinline__ ull pack2(float x, float y) {
    ull d;
    asm("mov.b64 %0, {%1, %2};" : "=l"(d) : "f"(x), "f"(y));
    return d;
}
__device__ __forceinline__ float2 unpack2(ull a) {
    float2 r;
    asm("mov.b64 {%0, %1}, %2;" : "=f"(r.x), "=f"(r.y) : "l"(a));
    return r;
}

// ---------------------------------------------------------------------------
// gar_feat [C][H*W] -> garT [H*W][C]  (coalesced gathers in warp kernel)
// grid (NP/32, CF/32), block (32, 8)
// ---------------------------------------------------------------------------
__global__ void transpose_gar(const float* __restrict__ gar, float* __restrict__ garT) {
    __shared__ float tile[32][33];
    int p0 = blockIdx.x * 32;   // pixel
    int c0 = blockIdx.y * 32;   // channel
    #pragma unroll
    for (int i = threadIdx.y; i < 32; i += 8)
        tile[i][threadIdx.x] = gar[(size_t)(c0 + i) * NP + p0 + threadIdx.x];
    __syncthreads();
    #pragma unroll
    for (int i = threadIdx.y; i < 32; i += 8)
        garT[(size_t)(p0 + i) * CF + c0 + threadIdx.x] = tile[threadIdx.x][i];
}

// ---------------------------------------------------------------------------
// Weight transpose: W [G][COUT_REAL][N]  ->  Wt [G][N][COUT_PAD], zero pad.
// N = CIN*9.  grid (N/32, ceil(COUT_PAD/32), G), block (32, 8)
// ---------------------------------------------------------------------------
__global__ void wtrans(const float* __restrict__ W, float* __restrict__ Wt,
                       int cout_real, int cout_pad, int N) {
    __shared__ float tile[32][33];
    int g  = blockIdx.z;
    int n0 = blockIdx.x * 32;
    int m0 = blockIdx.y * 32;
    #pragma unroll
    for (int i = threadIdx.y; i < 32; i += 8) {
        int m = m0 + i;
        int n = n0 + threadIdx.x;
        float v = 0.f;
        if (m < cout_real && n < N)
            v = W[((size_t)g * cout_real + m) * N + n];
        tile[i][threadIdx.x] = v;
    }
    __syncthreads();
    #pragma unroll
    for (int i = threadIdx.y; i < 32; i += 8) {
        int n = n0 + i;
        int m = m0 + threadIdx.x;
        if (n < N && m < cout_pad)
            Wt[((size_t)g * N + n) * cout_pad + m] = tile[threadIdx.x][i];
    }
}

// ---------------------------------------------------------------------------
// Implicit-GEMM 3x3 SAME conv.
// Tile: one full image row (64 px) x COUT_TILE output channels.
// Thread: 4 px (stride 16) x 4 couts (2 f32x2 pairs). K-chunks of 8 cin.
// wt layout: [G][CIN*9][COUT_PAD]; in layout: [G][CIN][NP] (or concat pair).
// out layout: [G][COUT_PAD][NP].
// ---------------------------------------------------------------------------
template<int CIN, int COUT_REAL, int COUT_PAD, int COUT_TILE, int THREADS, bool RELU, bool CONCAT>
__global__ __launch_bounds__(THREADS)
void conv3x3(const float* __restrict__ inA, const float* __restrict__ inB,
             const float* __restrict__ wt, const float* __restrict__ bias,
             float* __restrict__ out) {
    __shared__ float sIn[8 * 3 * 66];
    __shared__ float sW[8 * 9 * COUT_TILE];

    const int y        = blockIdx.x;
    const int coutBase = blockIdx.y * COUT_TILE;
    const int g        = blockIdx.z;
    const int tx       = threadIdx.x & 15;   // pixel group
    const int ty       = threadIdx.x >> 4;   // cout group

    ull acc[4][2];
    #pragma unroll
    for (int i = 0; i < 4; i++) { acc[i][0] = 0ull; acc[i][1] = 0ull; }

    const float* wbase = wt + (size_t)g * CIN * 9 * COUT_PAD + coutBase;

    for (int c0 = 0; c0 < CIN; c0 += 8) {
        const float* src;
        if (CONCAT)
            src = (c0 < 256) ? (inA + (size_t)c0 * NP) : (inB + (size_t)(c0 - 256) * NP);
        else
            src = inA + ((size_t)g * CIN + c0) * NP;

        // input patch: [8 cin][3 rows][66 cols] with zero halo
        for (int idx = threadIdx.x; idx < 8 * 3 * 66; idx += THREADS) {
            int cin = idx / 198;
            int rem = idx - cin * 198;
            int r   = rem / 66;
            int col = rem - r * 66;
            int yy  = y + r - 1;
            int xx  = col - 1;
            float v = 0.f;
            if (yy >= 0 && yy < HH && (unsigned)xx < (unsigned)WW)
                v = src[cin * NP + yy * WW + xx];
            sIn[idx] = v;
        }
        // weights: [8 cin * 9 taps][COUT_TILE]
        const float* wsrc = wbase + (size_t)c0 * 9 * COUT_PAD;
        for (int idx = threadIdx.x; idx < 8 * 9 * COUT_TILE; idx += THREADS) {
            int j  = idx / COUT_TILE;
            int co = idx - j * COUT_TILE;
            sW[idx] = wsrc[(size_t)j * COUT_PAD + co];
        }
        __syncthreads();

        #pragma unroll
        for (int cin = 0; cin < 8; cin++) {
            #pragma unroll
            for (int tap = 0; tap < 9; tap++) {
                const int r = tap / 3, s = tap - r * 3;
                const float* wrow = &sW[(cin * 9 + tap) * COUT_TILE + (ty << 2)];
                ull w01 = *(const ull*)(wrow);
                ull w23 = *(const ull*)(wrow + 2);
                const float* irow = &sIn[cin * 198 + r * 66 + s + tx];
                #pragma unroll
                for (int i = 0; i < 4; i++) {
                    float v = irow[i * 16];
                    ull vv = pack2(v, v);
                    acc[i][0] = fma2(vv, w01, acc[i][0]);
                    acc[i][1] = fma2(vv, w23, acc[i][1]);
                }
            }
        }
        __syncthreads();
    }

    // epilogue: bias (+ leaky relu), store
    #pragma unroll
    for (int j = 0; j < 4; j++) {
        int co = coutBase + (ty << 2) + j;
        float b = (co < COUT_REAL) ? bias[g * COUT_REAL + co] : 0.f;
        #pragma unroll
        for (int i = 0; i < 4; i++) {
            float2 pr = unpack2(acc[i][j >> 1]);
            float v = ((j & 1) ? pr.y : pr.x) + b;
            if (RELU) v = (v >= 0.f) ? v : 0.1f * v;
            out[((size_t)g * COUT_PAD + co) * NP + y * WW + tx + i * 16] = v;
        }
    }
}

// ---------------------------------------------------------------------------
// Final warp/sample kernel.
// Block = 256 threads, 4 pixels. Phase 1 (24 threads = 4px x 6k): cross-group
// softmax of attn logits + bilinear tap offsets/weights (attn folded in).
// Phase 2: thread c in [0,256): coalesced gathers from garT [HW][C].
// oa layout: [G][24][NP] (ch 0..11 = offsets, 12..17 = attn logits).
// ---------------------------------------------------------------------------
__global__ __launch_bounds__(256)
void warp_kernel(const float* __restrict__ oa, const float* __restrict__ garT,
                 const float* __restrict__ mask, float* __restrict__ out) {
    __shared__ int   sO[4][192];
    __shared__ float sA[4][192];

    const int pix0 = blockIdx.x * 4;
    const int t = threadIdx.x;

    if (t < 24) {
        int p = t / 6, k = t - (t / 6) * 6;
        int pix = pix0 + p;
        float fx = (float)(pix & 63);
        float fy = (float)(pix >> 6);
        float lg[8], ox[8], oy[8];
        #pragma unroll
        for (int g = 0; g < 8; g++) {
            const float* base = oa + (size_t)g * 24 * NP + pix;
            lg[g] = base[(12 + k) * NP];
            ox[g] = base[(2 * k) * NP];
            oy[g] = base[(2 * k + 1) * NP];
        }
        float m = lg[0];
        #pragma unroll
        for (int g = 1; g < 8; g++) m = fmaxf(m, lg[g]);
        float s = 0.f;
        #pragma unroll
        for (int g = 0; g < 8; g++) { lg[g] = expf(lg[g] - m); s += lg[g]; }
        float inv = 1.f / s;
        #pragma unroll
        for (int g = 0; g < 8; g++) {
            float attn = lg[g] * inv;
            // apply_offset + grid_sample(align_corners=False, border) composed:
            // xs = clip((x + ox) * 64/63 - 0.5, 0, 63)
            float xs = fminf(fmaxf((fx + ox[g]) * (64.0f / 63.0f) - 0.5f, 0.f), 63.f);
            float ys = fminf(fmaxf((fy + oy[g]) * (64.0f / 63.0f) - 0.5f, 0.f), 63.f);
            float x0f = floorf(xs), y0f = floorf(ys);
            float wx = xs - x0f, wy = ys - y0f;
            int x0 = (int)x0f, y0 = (int)y0f;
            int x1 = min(x0 + 1, 63), y1 = min(y0 + 1, 63);
            int q = (p * 6 + k) * 8 + g;
            sO[0][q] = (y0 * 64 + x0) * CF;
            sO[1][q] = (y0 * 64 + x1) * CF;
            sO[2][q] = (y1 * 64 + x0) * CF;
            sO[3][q] = (y1 * 64 + x1) * CF;
            sA[0][q] = attn * (1.f - wy) * (1.f - wx);
            sA[1][q] = attn * (1.f - wy) * wx;
            sA[2][q] = attn * wy * (1.f - wx);
            sA[3][q] = attn * wy * wx;
        }
    }
    __syncthreads();

    const int c = t;  // channel
    float mk[8];
    #pragma unroll
    for (int g = 0; g < 8; g++) mk[g] = mask[g * CF + c];

    for (int p = 0; p < 4; p++) {
        float accP = 0.f;
        for (int g = 0; g < 8; g++) {
            float accG = 0.f;
            #pragma unroll
            for (int k = 0; k < 6; k++) {
                int q = (p * 6 + k) * 8 + g;
                accG += sA[0][q] * garT[sO[0][q] + c]
                      + sA[1][q] * garT[sO[1][q] + c]
                      + sA[2][q] * garT[sO[2][q] + c]
                      + sA[3][q] * garT[sO[3][q] + c];
            }
            accP += accG * mk[g];
        }
        out[(size_t)c * NP + pix0 + p] = accP;
    }
}

// ---------------------------------------------------------------------------
extern "C" void kernel_launch(void* const* d_in, const int* in_sizes, int n_in,
                              void* d_out, int out_size) {
    const float* gar  = (const float*)d_in[0];
    const float* cond = (const float*)d_in[1];
    const float* mask = (const float*)d_in[2];
    const float* W1   = (const float*)d_in[3];
    const float* b1   = (const float*)d_in[4];
    const float* W2   = (const float*)d_in[5];
    const float* b2   = (const float*)d_in[6];
    const float* W3   = (const float*)d_in[7];
    const float* b3   = (const float*)d_in[8];
    const float* W4   = (const float*)d_in[9];
    const float* b4   = (const float*)d_in[10];
    float* out = (float*)d_out;

    float* S = nullptr;
    cudaGetSymbolAddress((void**)&S, g_scratch);
    float* garT = S + OFF_GART;
    float* wt1  = S + OFF_WT1;
    float* wt2  = S + OFF_WT2;
    float* wt3  = S + OFF_WT3;
    float* wt4  = S + OFF_WT4;
    float* hid1 = S + OFF_HID1;
    float* hid2 = S + OFF_HID2;
    float* hid3 = S + OFF_HID3;
    float* oa   = S + OFF_OA;

    transpose_gar<<<dim3(NP / 32, CF / 32), dim3(32, 8)>>>(gar, garT);
    wtrans<<<dim3(144, 4, NG), dim3(32, 8)>>>(W1, wt1, 128, 128, 512 * 9);
    wtrans<<<dim3(36,  2, NG), dim3(32, 8)>>>(W2, wt2, 64, 64, 128 * 9);
    wtrans<<<dim3(18,  1, NG), dim3(32, 8)>>>(W3, wt3, 32, 32, 64 * 9);
    wtrans<<<dim3(9,   1, NG), dim3(32, 8)>>>(W4, wt4, 18, 24, 32 * 9);

    conv3x3<512, 128, 128, 64, 256, true,  true ><<<dim3(HH, 2, NG), 256>>>(gar,  cond,    wt1, b1, hid1);
    conv3x3<128, 64,  64,  64, 256, true,  false><<<dim3(HH, 1, NG), 256>>>(hid1, nullptr, wt2, b2, hid2);
    conv3x3<64,  32,  32,  32, 128, true,  false><<<dim3(HH, 1, NG), 128>>>(hid2, nullptr, wt3, b3, hid3);
    conv3x3<32,  18,  24,  24, 96,  false, false><<<dim3(HH, 1, NG), 96 >>>(hid3, nullptr, wt4, b4, oa);

    warp_kernel<<<NP / 4, 256>>>(oa, garT, mask, out);
}

// round 4
// speedup vs baseline: 3.2531x; 3.2531x over previous
#include <cuda_runtime.h>
#include <cstdint>
#include <cstddef>

// ---------------------------------------------------------------------------
// DSDModules on GB300 via mma.sync tf32 (HMMA path; tcgen05 unavailable
// because the harness compiles through virtual arch compute_103, not 103a).
// Four 3x3 convs as implicit GEMM: M=128 pixels x N=couts, K=CIN*9 tap-major.
// cp.async double-buffered SMEM, XOR swizzle, fp32 register accumulators.
// Then cross-group softmax + K=6 deformable bilinear warp of gar (256ch).
// ---------------------------------------------------------------------------

#define NP 4096

// ---- scratch (floats) ------------------------------------------------------
#define OFF_INT  0ull
#define OFF_WB1  2097152ull
#define OFF_WB2  6815744ull
#define OFF_WB3  7405568ull
#define OFF_WB4  7553024ull
#define OFF_H1   7626752ull
#define OFF_H2   11821056ull
#define OFF_H3   13918208ull
#define OFF_OA   14966784ull
#define SCRATCH_FLOATS 15753216ull

__device__ __align__(1024) float g_scratch[SCRATCH_FLOATS];

// ---- helpers ---------------------------------------------------------------
__device__ __forceinline__ uint32_t smem_u32(const void* p) {
    uint32_t a;
    asm("{ .reg .u64 t; cvta.to.shared.u64 t, %1; cvt.u32.u64 %0, t; }"
        : "=r"(a) : "l"(p));
    return a;
}
__device__ __forceinline__ void cp16(uint32_t sa, const void* g, bool ok) {
    int sz = ok ? 16 : 0;
    asm volatile("cp.async.cg.shared.global [%0], [%1], 16, %2;"
                 :: "r"(sa), "l"(g), "r"(sz) : "memory");
}
#define CP_COMMIT() asm volatile("cp.async.commit_group;" ::: "memory")
#define CP_WAIT(n)  asm volatile("cp.async.wait_group %0;" :: "n"(n) : "memory")

__device__ __forceinline__ uint32_t f2tf(float f) {
    uint32_t u;
    asm("cvt.rna.tf32.f32 %0, %1;" : "=r"(u) : "f"(f));
    return u;
}
__device__ __forceinline__ void mma_tf32(float* c, const uint32_t* a, const uint32_t* b) {
    asm volatile(
        "mma.sync.aligned.m16n8k8.row.col.f32.tf32.tf32.f32 "
        "{%0,%1,%2,%3}, {%4,%5,%6,%7}, {%8,%9}, {%0,%1,%2,%3};"
        : "+f"(c[0]), "+f"(c[1]), "+f"(c[2]), "+f"(c[3])
        : "r"(a[0]), "r"(a[1]), "r"(a[2]), "r"(a[3]), "r"(b[0]), "r"(b[1]));
}

// ---------------------------------------------------------------------------
// concat(gar, cond) [512][4096] -> inT [4096][512]
// ---------------------------------------------------------------------------
__global__ void transpose_in(const float* __restrict__ gar,
                             const float* __restrict__ cond,
                             float* __restrict__ inT) {
    __shared__ float tile[32][33];
    int p0 = blockIdx.x * 32;
    int c0 = blockIdx.y * 32;
    for (int i = threadIdx.y; i < 32; i += 8) {
        int c = c0 + i;
        const float* src = (c < 256) ? (gar + (size_t)c * NP) : (cond + (size_t)(c - 256) * NP);
        tile[i][threadIdx.x] = src[p0 + threadIdx.x];
    }
    __syncthreads();
    for (int i = threadIdx.y; i < 32; i += 8)
        inT[(size_t)(p0 + i) * 512 + c0 + threadIdx.x] = tile[threadIdx.x][i];
}

// ---------------------------------------------------------------------------
// Weight reorder: W [G][COUT_REAL][CIN][3][3] -> Wb [G][COUT_PAD][CIN*9],
// K index = tap*CIN + cin (tap-major), zero pad couts.
// ---------------------------------------------------------------------------
__global__ void wbprep(const float* __restrict__ W, float* __restrict__ Wb,
                       int CIN, int COUT_REAL, int COUT_PAD) {
    int K = CIN * 9;
    size_t total = (size_t)8 * COUT_PAD * K;
    for (size_t i = (size_t)blockIdx.x * blockDim.x + threadIdx.x; i < total;
         i += (size_t)gridDim.x * blockDim.x) {
        int k = (int)(i % K);
        size_t rem = i / K;
        int m = (int)(rem % COUT_PAD);
        int g = (int)(rem / COUT_PAD);
        int tap = k / CIN, cin = k - tap * CIN;
        float v = 0.f;
        if (m < COUT_REAL)
            v = W[((size_t)(g * COUT_REAL + m) * CIN + cin) * 9 + tap];
        Wb[i] = v;
    }
}

// ---------------------------------------------------------------------------
// mma.sync tf32 implicit-GEMM 3x3 conv.
//   in:  [g][4096][CIN] (gstride floats between groups; 0 => shared input)
//   Wb:  [G][COUT][K] tap-major
//   OUT_MODE 0: out[g][pix][COUT_REAL]   (transposed, next conv's input)
//   OUT_MODE 1: out[g][cout][NP]         (channel-major, final oa)
// grid (32 pixel-tiles, 8 groups), 128 threads (4 warps).
// ---------------------------------------------------------------------------
template<int CIN, int COUT, int COUT_REAL, bool RELU, int OUT_MODE>
__global__ __launch_bounds__(128, 2)
void mconv(const float* __restrict__ in, size_t gstride,
           const float* __restrict__ Wb, const float* __restrict__ bias,
           float* __restrict__ out) {
    constexpr int K       = CIN * 9;
    constexpr int NCH     = K / 32;
    constexpr int CPT     = CIN / 32;
    constexpr int WARPS_N = (COUT >= 64) ? 2 : 1;
    constexpr int WARPS_M = 4 / WARPS_N;
    constexpr int WM      = 128 / WARPS_M;
    constexpr int WN      = COUT / WARPS_N;
    constexpr int MT      = WM / 16;
    constexpr int NTT     = WN / 8;
    constexpr int ASZ     = 16384;          // 128 rows x 128B
    constexpr int BSZ     = COUT * 128;

    extern __shared__ char sm[];
    uint32_t dyn = smem_u32(sm);
    uint32_t base = (dyn + 1023u) & ~1023u;
    char* cbase = sm + (base - dyn);

    const int tid  = threadIdx.x;
    const int warp = tid >> 5;
    const int lane = tid & 31;
    const int lq   = lane >> 2;
    const int lc   = lane & 3;
    const int wm   = warp % WARPS_M;
    const int wn   = warp / WARPS_M;
    const int t    = blockIdx.x;
    const int g    = blockIdx.y;

    const float* inb = in + (size_t)g * gstride;
    const float* wg  = Wb + (size_t)g * COUT * K;

    uint32_t aAddr[2] = { base, base + ASZ };
    uint32_t bAddr[2] = { base + 2 * ASZ, base + 2 * ASZ + BSZ };
    char* aPtr[2] = { cbase, cbase + ASZ };
    char* bPtr[2] = { cbase + 2 * ASZ, cbase + 2 * ASZ + BSZ };

    float acc[MT][NTT][4];
    #pragma unroll
    for (int i = 0; i < MT; i++)
        #pragma unroll
        for (int j = 0; j < NTT; j++)
            #pragma unroll
            for (int q = 0; q < 4; q++) acc[i][j][q] = 0.f;

    auto load_chunk = [&](int kc, int buf) {
        int tap = kc / CPT;
        int c0  = (kc - tap * CPT) * 32;
        int r   = tap / 3 - 1;
        int s   = tap - 3 * (tap / 3) - 1;
        #pragma unroll
        for (int i = 0; i < 8; i++) {
            int idx = i * 128 + tid;
            int p   = idx >> 3, seg = idx & 7;
            int yy  = 2 * t + (p >> 6) + r;
            int xx  = (p & 63) + s;
            bool ok = ((unsigned)yy < 64u) & ((unsigned)xx < 64u);
            int yc = ok ? yy : 0, xc = ok ? xx : 0;
            const float* gp = inb + (size_t)(yc * 64 + xc) * CIN + c0 + seg * 4;
            uint32_t sa = aAddr[buf] + (uint32_t)(p * 128 + ((seg * 16) ^ ((p & 7) * 16)));
            cp16(sa, gp, ok);
        }
        #pragma unroll
        for (int i = 0; i < COUT / 16; i++) {
            int idx = i * 128 + tid;
            int m   = idx >> 3, seg = idx & 7;
            const float* gp = wg + (size_t)m * K + kc * 32 + seg * 4;
            uint32_t sb = bAddr[buf] + (uint32_t)(m * 128 + ((seg * 16) ^ ((m & 7) * 16)));
            cp16(sb, gp, true);
        }
        CP_COMMIT();
    };

    auto compute_chunk = [&](int buf) {
        const char* aB = aPtr[buf];
        const char* bB = bPtr[buf];
        #pragma unroll
        for (int kk = 0; kk < 4; kk++) {
            int cb0 = kk * 32 + lc * 4;   // byte offset of k column (lo)
            int cb1 = cb0 + 16;           // +4 floats
            uint32_t afr[MT][4];
            #pragma unroll
            for (int mt = 0; mt < MT; mt++) {
                int row = wm * WM + mt * 16 + lq;
                int rx  = (row & 7) * 16;
                int r0  = row * 128;
                int r8  = (row + 8) * 128;
                afr[mt][0] = f2tf(*(const float*)(aB + r0 + (cb0 ^ rx)));
                afr[mt][1] = f2tf(*(const float*)(aB + r8 + (cb0 ^ rx)));
                afr[mt][2] = f2tf(*(const float*)(aB + r0 + (cb1 ^ rx)));
                afr[mt][3] = f2tf(*(const float*)(aB + r8 + (cb1 ^ rx)));
            }
            uint32_t bfr[NTT][2];
            #pragma unroll
            for (int nt = 0; nt < NTT; nt++) {
                int n  = wn * WN + nt * 8 + lq;
                int nx = (n & 7) * 16;
                int nb = n * 128;
                bfr[nt][0] = f2tf(*(const float*)(bB + nb + (cb0 ^ nx)));
                bfr[nt][1] = f2tf(*(const float*)(bB + nb + (cb1 ^ nx)));
            }
            #pragma unroll
            for (int mt = 0; mt < MT; mt++)
                #pragma unroll
                for (int nt = 0; nt < NTT; nt++)
                    mma_tf32(acc[mt][nt], afr[mt], bfr[nt]);
        }
    };

    load_chunk(0, 0);
    for (int kc = 0; kc < NCH; kc++) {
        int buf = kc & 1;
        if (kc + 1 < NCH) {
            __syncthreads();                 // everyone done reading buf^1
            load_chunk(kc + 1, buf ^ 1);
            CP_WAIT(1);                      // chunk kc arrived
        } else {
            CP_WAIT(0);
        }
        __syncthreads();
        compute_chunk(buf);
    }

    // Epilogue: bias + lrelu, store.
    #pragma unroll
    for (int mt = 0; mt < MT; mt++) {
        int row0 = t * 128 + wm * WM + mt * 16 + lq;   // global pixel
        #pragma unroll
        for (int nt = 0; nt < NTT; nt++) {
            int n0 = wn * WN + nt * 8 + lc * 2;
            float b0 = (n0     < COUT_REAL) ? bias[g * COUT_REAL + n0]     : 0.f;
            float b1 = (n0 + 1 < COUT_REAL) ? bias[g * COUT_REAL + n0 + 1] : 0.f;
            #pragma unroll
            for (int h = 0; h < 2; h++) {
                int pix = row0 + h * 8;
                float v0 = acc[mt][nt][h * 2]     + b0;
                float v1 = acc[mt][nt][h * 2 + 1] + b1;
                if (RELU) {
                    v0 = (v0 >= 0.f) ? v0 : 0.1f * v0;
                    v1 = (v1 >= 0.f) ? v1 : 0.1f * v1;
                }
                if (OUT_MODE == 0) {
                    float2* dst = (float2*)(out + ((size_t)g * NP + pix) * COUT_REAL + n0);
                    *dst = make_float2(v0, v1);
                } else {
                    if (n0 < COUT_REAL)
                        out[(size_t)(g * COUT_REAL + n0) * NP + pix] = v0;
                    if (n0 + 1 < COUT_REAL)
                        out[(size_t)(g * COUT_REAL + n0 + 1) * NP + pix] = v1;
                }
            }
        }
    }
}

// ---------------------------------------------------------------------------
// Final warp/sample kernel. oa layout [G][18][NP]; gathers from inT[pix][512]
// (first 256 channels are gar_feat).
// ---------------------------------------------------------------------------
__global__ __launch_bounds__(256)
void warp_kernel(const float* __restrict__ oa, const float* __restrict__ inT,
                 const float* __restrict__ mask, float* __restrict__ out) {
    __shared__ int   sO[4][192];
    __shared__ float sA[4][192];

    const int pix0 = blockIdx.x * 4;
    const int tt = threadIdx.x;

    if (tt < 24) {
        int p = tt / 6, k = tt - (tt / 6) * 6;
        int pix = pix0 + p;
        float fx = (float)(pix & 63);
        float fy = (float)(pix >> 6);
        float lg[8], ox[8], oy[8];
        #pragma unroll
        for (int g = 0; g < 8; g++) {
            const float* base = oa + (size_t)g * 18 * NP + pix;
            lg[g] = base[(12 + k) * NP];
            ox[g] = base[(2 * k) * NP];
            oy[g] = base[(2 * k + 1) * NP];
        }
        float m = lg[0];
        #pragma unroll
        for (int g = 1; g < 8; g++) m = fmaxf(m, lg[g]);
        float s = 0.f;
        #pragma unroll
        for (int g = 0; g < 8; g++) { lg[g] = expf(lg[g] - m); s += lg[g]; }
        float inv = 1.f / s;
        #pragma unroll
        for (int g = 0; g < 8; g++) {
            float attn = lg[g] * inv;
            float xs = fminf(fmaxf((fx + ox[g]) * (64.0f / 63.0f) - 0.5f, 0.f), 63.f);
            float ys = fminf(fmaxf((fy + oy[g]) * (64.0f / 63.0f) - 0.5f, 0.f), 63.f);
            float x0f = floorf(xs), y0f = floorf(ys);
            float wx = xs - x0f, wy = ys - y0f;
            int x0 = (int)x0f, y0 = (int)y0f;
            int x1 = min(x0 + 1, 63), y1 = min(y0 + 1, 63);
            int q = (p * 6 + k) * 8 + g;
            sO[0][q] = (y0 * 64 + x0) * 512;
            sO[1][q] = (y0 * 64 + x1) * 512;
            sO[2][q] = (y1 * 64 + x0) * 512;
            sO[3][q] = (y1 * 64 + x1) * 512;
            sA[0][q] = attn * (1.f - wy) * (1.f - wx);
            sA[1][q] = attn * (1.f - wy) * wx;
            sA[2][q] = attn * wy * (1.f - wx);
            sA[3][q] = attn * wy * wx;
        }
    }
    __syncthreads();

    const int c = tt;  // channel (gar channels are inT cols 0..255)
    float mk[8];
    #pragma unroll
    for (int g = 0; g < 8; g++) mk[g] = mask[g * 256 + c];

    for (int p = 0; p < 4; p++) {
        float accP = 0.f;
        for (int g = 0; g < 8; g++) {
            float accG = 0.f;
            #pragma unroll
            for (int k = 0; k < 6; k++) {
                int q = (p * 6 + k) * 8 + g;
                accG += sA[0][q] * inT[sO[0][q] + c]
                      + sA[1][q] * inT[sO[1][q] + c]
                      + sA[2][q] * inT[sO[2][q] + c]
                      + sA[3][q] * inT[sO[3][q] + c];
            }
            accP += accG * mk[g];
        }
        out[(size_t)c * NP + pix0 + p] = accP;
    }
}

// ---------------------------------------------------------------------------
extern "C" void kernel_launch(void* const* d_in, const int* in_sizes, int n_in,
                              void* d_out, int out_size) {
    const float* gar  = (const float*)d_in[0];
    const float* cond = (const float*)d_in[1];
    const float* mask = (const float*)d_in[2];
    const float* W1   = (const float*)d_in[3];
    const float* b1   = (const float*)d_in[4];
    const float* W2   = (const float*)d_in[5];
    const float* b2   = (const float*)d_in[6];
    const float* W3   = (const float*)d_in[7];
    const float* b3   = (const float*)d_in[8];
    const float* W4   = (const float*)d_in[9];
    const float* b4   = (const float*)d_in[10];
    float* out = (float*)d_out;

    float* S = nullptr;
    cudaGetSymbolAddress((void**)&S, g_scratch);
    float* inT = S + OFF_INT;
    float* wb1 = S + OFF_WB1;
    float* wb2 = S + OFF_WB2;
    float* wb3 = S + OFF_WB3;
    float* wb4 = S + OFF_WB4;
    float* h1  = S + OFF_H1;
    float* h2  = S + OFF_H2;
    float* h3  = S + OFF_H3;
    float* oa  = S + OFF_OA;

    cudaFuncSetAttribute(mconv<512,128,128,true ,0>, cudaFuncAttributeMaxDynamicSharedMemorySize, 66560);
    cudaFuncSetAttribute(mconv<128, 64, 64,true ,0>, cudaFuncAttributeMaxDynamicSharedMemorySize, 50176);
    cudaFuncSetAttribute(mconv< 64, 32, 32,true ,0>, cudaFuncAttributeMaxDynamicSharedMemorySize, 41984);
    cudaFuncSetAttribute(mconv< 32, 32, 18,false,1>, cudaFuncAttributeMaxDynamicSharedMemorySize, 41984);

    transpose_in<<<dim3(NP / 32, 16), dim3(32, 8)>>>(gar, cond, inT);
    wbprep<<<4096, 256>>>(W1, wb1, 512, 128, 128);
    wbprep<<<1024, 256>>>(W2, wb2, 128,  64,  64);
    wbprep<<< 512, 256>>>(W3, wb3,  64,  32,  32);
    wbprep<<< 256, 256>>>(W4, wb4,  32,  18,  32);

    mconv<512,128,128,true ,0><<<dim3(32, 8), 128, 66560>>>(inT, 0,                wb1, b1, h1);
    mconv<128, 64, 64,true ,0><<<dim3(32, 8), 128, 50176>>>(h1, (size_t)NP * 128,  wb2, b2, h2);
    mconv< 64, 32, 32,true ,0><<<dim3(32, 8), 128, 41984>>>(h2, (size_t)NP * 64,   wb3, b3, h3);
    mconv< 32, 32, 18,false,1><<<dim3(32, 8), 128, 41984>>>(h3, (size_t)NP * 32,   wb4, b4, oa);

    warp_kernel<<<NP / 4, 256>>>(oa, inT, mask, out);
}

// round 5
// speedup vs baseline: 3.4338x; 1.0555x over previous
#include <cuda_runtime.h>
#include <cstdint>
#include <cstddef>

// ---------------------------------------------------------------------------
// DSDModules via mma.sync tf32 (HMMA; tcgen05 unavailable through compute_103
// virtual arch). v2: band-reuse implicit-GEMM conv (9x less A traffic),
// M=256 tiles (2x less B traffic), pre-rounded tf32 operands (no cvt in hot
// loop), LDS.128 fragments, 2-stream ordered cp.async pipeline.
// ---------------------------------------------------------------------------

#define NP 4096

// ---- scratch offsets (floats) ----------------------------------------------
#define OFF_INT  0ull            // inT   [4096][512]  tf32-rounded
#define OFF_GART 2097152ull      // garT  [4096][256]  fp32
#define OFF_WB1  3145728ull      // wb1   [8][128][4608] tf32
#define OFF_WB2  7864320ull
#define OFF_WB3  8454144ull
#define OFF_WB4  8601600ull
#define OFF_H1   8675328ull      // h1 [8][4096][128] tf32
#define OFF_H2   12869632ull
#define OFF_H3   14966784ull
#define OFF_OA   16015360ull     // oa [8][18][4096] fp32
#define SCRATCH_FLOATS 16605184ull

__device__ __align__(1024) float g_scratch[SCRATCH_FLOATS];

// ---- helpers ---------------------------------------------------------------
__device__ __forceinline__ uint32_t smem_u32(const void* p) {
    uint32_t a;
    asm("{ .reg .u64 t; cvta.to.shared.u64 t, %1; cvt.u32.u64 %0, t; }"
        : "=r"(a) : "l"(p));
    return a;
}
__device__ __forceinline__ void cp16(uint32_t sa, const void* g, bool ok) {
    int sz = ok ? 16 : 0;
    asm volatile("cp.async.cg.shared.global [%0], [%1], 16, %2;"
                 :: "r"(sa), "l"(g), "r"(sz) : "memory");
}
#define CP_COMMIT() asm volatile("cp.async.commit_group;" ::: "memory")
#define CP_WAIT(n)  asm volatile("cp.async.wait_group %0;" :: "n"(n) : "memory")

__device__ __forceinline__ float f2tf(float f) {
    uint32_t u;
    asm("cvt.rna.tf32.f32 %0, %1;" : "=r"(u) : "f"(f));
    return __uint_as_float(u);
}
__device__ __forceinline__ void mma_tf32(float* c, const uint32_t* a, const uint32_t* b) {
    asm volatile(
        "mma.sync.aligned.m16n8k8.row.col.f32.tf32.tf32.f32 "
        "{%0,%1,%2,%3}, {%4,%5,%6,%7}, {%8,%9}, {%0,%1,%2,%3};"
        : "+f"(c[0]), "+f"(c[1]), "+f"(c[2]), "+f"(c[3])
        : "r"(a[0]), "r"(a[1]), "r"(a[2]), "r"(a[3]), "r"(b[0]), "r"(b[1]));
}

// ---------------------------------------------------------------------------
// concat(gar, cond) [512][4096] -> inT [4096][512] (tf32-rounded)
//                                  garT [4096][256] (fp32, gar only)
// ---------------------------------------------------------------------------
__global__ void transpose_in(const float* __restrict__ gar,
                             const float* __restrict__ cond,
                             float* __restrict__ inT,
                             float* __restrict__ garT) {
    __shared__ float tile[32][33];
    int p0 = blockIdx.x * 32;
    int c0 = blockIdx.y * 32;
    for (int i = threadIdx.y; i < 32; i += 8) {
        int c = c0 + i;
        const float* src = (c < 256) ? (gar + (size_t)c * NP) : (cond + (size_t)(c - 256) * NP);
        tile[i][threadIdx.x] = src[p0 + threadIdx.x];
    }
    __syncthreads();
    for (int i = threadIdx.y; i < 32; i += 8) {
        float v = tile[threadIdx.x][i];
        int pix = p0 + i, c = c0 + threadIdx.x;
        inT[(size_t)pix * 512 + c] = f2tf(v);
        if (c0 < 256)
            garT[(size_t)pix * 256 + c] = v;
    }
}

// ---------------------------------------------------------------------------
// W [G][COUT_REAL][CIN][3][3] -> Wb [G][COUT_PAD][K], K = tap*CIN + cin,
// tf32-rounded, zero-padded couts. Compile-time divides.
// ---------------------------------------------------------------------------
template<int CIN, int COUT_REAL, int COUT_PAD>
__global__ void wbprep(const float* __restrict__ W, float* __restrict__ Wb) {
    constexpr int K = CIN * 9;
    constexpr size_t total = (size_t)8 * COUT_PAD * K;
    for (size_t i = (size_t)blockIdx.x * blockDim.x + threadIdx.x; i < total;
         i += (size_t)gridDim.x * blockDim.x) {
        int k = (int)(i % K);
        size_t rem = i / K;
        int m = (int)(rem % COUT_PAD);
        int g = (int)(rem / COUT_PAD);
        int tap = k / CIN, cin = k - tap * CIN;
        float v = 0.f;
        if (m < COUT_REAL)
            v = W[((size_t)(g * COUT_REAL + m) * CIN + cin) * 9 + tap];
        Wb[i] = f2tf(v);
    }
}

// ---------------------------------------------------------------------------
// Band-reuse tf32 implicit-GEMM 3x3 conv.
//   CTA: 256 px (4 image rows) x COUT, 256 threads (8 warps: 4 M x 2 N).
//   Band: 6 rows x 66 cols x 32 cin (zero halo), loaded once per cin-chunk,
//   reused by all 9 taps. B: COUT x 32 floats per tap-chunk, double-buffered.
//   in: [g][4096][CIN] (gstride floats between groups; 0 => shared input).
//   OUT_MODE 0: out[g][pix][COUT] tf32-rounded. OUT_MODE 1: out[g][m][NP] fp32.
// grid (16, 8).
// ---------------------------------------------------------------------------
template<int CIN, int COUT, int COUT_REAL, bool RELU, int OUT_MODE>
__global__ __launch_bounds__(256, 1)
void mconv(const float* __restrict__ in, size_t gstride,
           const float* __restrict__ Wb, const float* __restrict__ bias,
           float* __restrict__ out) {
    constexpr int K      = CIN * 9;
    constexpr int NCC    = CIN / 32;          // cin chunks
    constexpr int TOT    = NCC * 9;           // tap-chunks
    constexpr int WN     = COUT / 2;
    constexpr int NTT    = WN / 8;
    constexpr int BPIX   = 396;               // 6 rows x 66 cols
    constexpr int BSTAGE = BPIX * 128;        // bytes
    constexpr int BBS    = COUT * 128;        // B stage bytes

    extern __shared__ char sm[];
    uint32_t dyn  = smem_u32(sm);
    uint32_t base = (dyn + 1023u) & ~1023u;
    char*    cb   = sm + (base - dyn);

    const int tid  = threadIdx.x;
    const int warp = tid >> 5;
    const int lane = tid & 31;
    const int lq   = lane >> 2;
    const int lc   = lane & 3;
    const int wm   = warp & 3;
    const int wn   = warp >> 2;
    const int tile = blockIdx.x;
    const int g    = blockIdx.y;
    const int y0   = tile * 4 - 1;

    const float* src = in + (size_t)g * gstride;
    const float* wg  = Wb + (size_t)g * COUT * K;

    uint32_t bandA[2] = { base, base + BSTAGE };
    uint32_t bbA[2]   = { base + 2 * BSTAGE, base + 2 * BSTAGE + BBS };
    char* bandP[2] = { cb, cb + BSTAGE };
    char* bbP[2]   = { cb + 2 * BSTAGE, cb + 2 * BSTAGE + BBS };

    float acc[4][NTT][4];
    #pragma unroll
    for (int i = 0; i < 4; i++)
        #pragma unroll
        for (int j = 0; j < NTT; j++)
            #pragma unroll
            for (int q = 0; q < 4; q++) acc[i][j][q] = 0.f;

    auto band_load = [&](int cc, int buf) {
        int c0 = cc * 32;
        for (int it = tid; it < BPIX * 8; it += 256) {
            int bp = it >> 3, seg = it & 7;
            int br = bp / 66;
            int col = bp - br * 66;
            int y = y0 + br, x = col - 1;
            bool ok = ((unsigned)y < 64u) & ((unsigned)x < 64u);
            int pix = ok ? (y * 64 + x) : 0;
            const float* gp = src + (size_t)pix * CIN + c0 + seg * 4;
            cp16(bandA[buf] + (uint32_t)(bp * 128 + ((seg * 16) ^ ((bp & 7) * 16))), gp, ok);
        }
    };
    auto b_load = [&](int kc, int buf) {
        int cc = kc / 9;
        int koff = (kc - cc * 9) * CIN + cc * 32;
        for (int it = tid; it < COUT * 8; it += 256) {
            int m = it >> 3, seg = it & 7;
            const float* gp = wg + (size_t)m * K + koff + seg * 4;
            cp16(bbA[buf] + (uint32_t)(m * 128 + ((seg * 16) ^ ((m & 7) * 16))), gp, true);
        }
    };

    auto compute = [&](int tap, int bandbuf, int bbuf) {
        int r = tap / 3, s = tap - 3 * (tap / 3);
        int bb = (wm + r) * 66 + s + lq;
        const char* aB = bandP[bandbuf];
        const char* bB = bbP[bbuf];
        #pragma unroll
        for (int h = 0; h < 2; h++) {
            int cbyte = 32 * lc + 16 * h;
            float4 a4[8];
            #pragma unroll
            for (int mt = 0; mt < 4; mt++) {
                int bp0 = bb + mt * 16;
                int bp1 = bp0 + 8;
                a4[2 * mt]     = *(const float4*)(aB + bp0 * 128 + (cbyte ^ ((bp0 & 7) * 16)));
                a4[2 * mt + 1] = *(const float4*)(aB + bp1 * 128 + (cbyte ^ ((bp1 & 7) * 16)));
            }
            float4 b4[NTT];
            #pragma unroll
            for (int nt = 0; nt < NTT; nt++) {
                int n = wn * WN + nt * 8 + lq;
                b4[nt] = *(const float4*)(bB + n * 128 + (cbyte ^ ((n & 7) * 16)));
            }
            // j = 0 (.x,.y), j = 1 (.z,.w)
            #pragma unroll
            for (int mt = 0; mt < 4; mt++) {
                uint32_t af0[4] = { __float_as_uint(a4[2*mt].x), __float_as_uint(a4[2*mt+1].x),
                                    __float_as_uint(a4[2*mt].y), __float_as_uint(a4[2*mt+1].y) };
                uint32_t af1[4] = { __float_as_uint(a4[2*mt].z), __float_as_uint(a4[2*mt+1].z),
                                    __float_as_uint(a4[2*mt].w), __float_as_uint(a4[2*mt+1].w) };
                #pragma unroll
                for (int nt = 0; nt < NTT; nt++) {
                    uint32_t bf0[2] = { __float_as_uint(b4[nt].x), __float_as_uint(b4[nt].y) };
                    uint32_t bf1[2] = { __float_as_uint(b4[nt].z), __float_as_uint(b4[nt].w) };
                    mma_tf32(acc[mt][nt], af0, bf0);
                    mma_tf32(acc[mt][nt], af1, bf1);
                }
            }
        }
    };

    band_load(0, 0); CP_COMMIT();
    b_load(0, 0);    CP_COMMIT();

    for (int kc = 0; kc < TOT; kc++) {
        int cc  = kc / 9;
        int tap = kc - cc * 9;
        if (tap == 8 && cc + 1 < NCC) {
            band_load(cc + 1, (cc + 1) & 1); CP_COMMIT();
            b_load(kc + 1, (kc + 1) & 1);    CP_COMMIT();
            CP_WAIT(2);
        } else if (kc + 1 < TOT) {
            b_load(kc + 1, (kc + 1) & 1);    CP_COMMIT();
            CP_WAIT(1);
        } else {
            CP_WAIT(0);
        }
        __syncthreads();
        compute(tap, cc & 1, kc & 1);
        __syncthreads();
    }

    // Epilogue: bias + lrelu (+ tf32 round for OUT_MODE 0), store.
    #pragma unroll
    for (int mt = 0; mt < 4; mt++) {
        int prow = tile * 256 + wm * 64 + mt * 16 + lq;
        #pragma unroll
        for (int nt = 0; nt < NTT; nt++) {
            int n0 = wn * WN + nt * 8 + lc * 2;
            float b0 = (n0     < COUT_REAL) ? bias[g * COUT_REAL + n0]     : 0.f;
            float b1 = (n0 + 1 < COUT_REAL) ? bias[g * COUT_REAL + n0 + 1] : 0.f;
            #pragma unroll
            for (int h = 0; h < 2; h++) {
                int p = prow + h * 8;
                float v0 = acc[mt][nt][h * 2]     + b0;
                float v1 = acc[mt][nt][h * 2 + 1] + b1;
                if (RELU) {
                    v0 = (v0 >= 0.f) ? v0 : 0.1f * v0;
                    v1 = (v1 >= 0.f) ? v1 : 0.1f * v1;
                }
                if (OUT_MODE == 0) {
                    float2* dst = (float2*)(out + ((size_t)g * NP + p) * COUT + n0);
                    *dst = make_float2(f2tf(v0), f2tf(v1));
                } else {
                    if (n0 < COUT_REAL)
                        out[(size_t)(g * COUT_REAL + n0) * NP + p] = v0;
                    if (n0 + 1 < COUT_REAL)
                        out[(size_t)(g * COUT_REAL + n0 + 1) * NP + p] = v1;
                }
            }
        }
    }
}

// ---------------------------------------------------------------------------
// Final warp/sample kernel. oa [G][18][NP]; gathers from garT [4096][256].
// ---------------------------------------------------------------------------
__global__ __launch_bounds__(256)
void warp_kernel(const float* __restrict__ oa, const float* __restrict__ garT,
                 const float* __restrict__ mask, float* __restrict__ out) {
    __shared__ int   sO[4][192];
    __shared__ float sA[4][192];

    const int pix0 = blockIdx.x * 4;
    const int tt = threadIdx.x;

    if (tt < 24) {
        int p = tt / 6, k = tt - (tt / 6) * 6;
        int pix = pix0 + p;
        float fx = (float)(pix & 63);
        float fy = (float)(pix >> 6);
        float lg[8], ox[8], oy[8];
        #pragma unroll
        for (int g = 0; g < 8; g++) {
            const float* base = oa + (size_t)g * 18 * NP + pix;
            lg[g] = base[(12 + k) * NP];
            ox[g] = base[(2 * k) * NP];
            oy[g] = base[(2 * k + 1) * NP];
        }
        float m = lg[0];
        #pragma unroll
        for (int g = 1; g < 8; g++) m = fmaxf(m, lg[g]);
        float s = 0.f;
        #pragma unroll
        for (int g = 0; g < 8; g++) { lg[g] = expf(lg[g] - m); s += lg[g]; }
        float inv = 1.f / s;
        #pragma unroll
        for (int g = 0; g < 8; g++) {
            float attn = lg[g] * inv;
            float xs = fminf(fmaxf((fx + ox[g]) * (64.0f / 63.0f) - 0.5f, 0.f), 63.f);
            float ys = fminf(fmaxf((fy + oy[g]) * (64.0f / 63.0f) - 0.5f, 0.f), 63.f);
            float x0f = floorf(xs), y0f = floorf(ys);
            float wx = xs - x0f, wy = ys - y0f;
            int x0 = (int)x0f, y0 = (int)y0f;
            int x1 = min(x0 + 1, 63), y1 = min(y0 + 1, 63);
            int q = (p * 6 + k) * 8 + g;
            sO[0][q] = (y0 * 64 + x0) * 256;
            sO[1][q] = (y0 * 64 + x1) * 256;
            sO[2][q] = (y1 * 64 + x0) * 256;
            sO[3][q] = (y1 * 64 + x1) * 256;
            sA[0][q] = attn * (1.f - wy) * (1.f - wx);
            sA[1][q] = attn * (1.f - wy) * wx;
            sA[2][q] = attn * wy * (1.f - wx);
            sA[3][q] = attn * wy * wx;
        }
    }
    __syncthreads();

    const int c = tt;  // channel
    float mk[8];
    #pragma unroll
    for (int g = 0; g < 8; g++) mk[g] = mask[g * 256 + c];

    for (int p = 0; p < 4; p++) {
        float accP = 0.f;
        for (int g = 0; g < 8; g++) {
            float accG = 0.f;
            #pragma unroll
            for (int k = 0; k < 6; k++) {
                int q = (p * 6 + k) * 8 + g;
                accG += sA[0][q] * garT[sO[0][q] + c]
                      + sA[1][q] * garT[sO[1][q] + c]
                      + sA[2][q] * garT[sO[2][q] + c]
                      + sA[3][q] * garT[sO[3][q] + c];
            }
            accP += accG * mk[g];
        }
        out[(size_t)c * NP + pix0 + p] = accP;
    }
}

// ---------------------------------------------------------------------------
extern "C" void kernel_launch(void* const* d_in, const int* in_sizes, int n_in,
                              void* d_out, int out_size) {
    const float* gar  = (const float*)d_in[0];
    const float* cond = (const float*)d_in[1];
    const float* mask = (const float*)d_in[2];
    const float* W1   = (const float*)d_in[3];
    const float* b1   = (const float*)d_in[4];
    const float* W2   = (const float*)d_in[5];
    const float* b2   = (const float*)d_in[6];
    const float* W3   = (const float*)d_in[7];
    const float* b3   = (const float*)d_in[8];
    const float* W4   = (const float*)d_in[9];
    const float* b4   = (const float*)d_in[10];
    float* out = (float*)d_out;

    float* S = nullptr;
    cudaGetSymbolAddress((void**)&S, g_scratch);
    float* inT  = S + OFF_INT;
    float* garT = S + OFF_GART;
    float* wb1  = S + OFF_WB1;
    float* wb2  = S + OFF_WB2;
    float* wb3  = S + OFF_WB3;
    float* wb4  = S + OFF_WB4;
    float* h1   = S + OFF_H1;
    float* h2   = S + OFF_H2;
    float* h3   = S + OFF_H3;
    float* oa   = S + OFF_OA;

    cudaFuncSetAttribute(mconv<512,128,128,true ,0>, cudaFuncAttributeMaxDynamicSharedMemorySize, 135168);
    cudaFuncSetAttribute(mconv<128, 64, 64,true ,0>, cudaFuncAttributeMaxDynamicSharedMemorySize, 118784);
    cudaFuncSetAttribute(mconv< 64, 32, 32,true ,0>, cudaFuncAttributeMaxDynamicSharedMemorySize, 110592);
    cudaFuncSetAttribute(mconv< 32, 32, 18,false,1>, cudaFuncAttributeMaxDynamicSharedMemorySize, 110592);

    transpose_in<<<dim3(128, 16), dim3(32, 8)>>>(gar, cond, inT, garT);
    wbprep<512, 128, 128><<<4096, 256>>>(W1, wb1);
    wbprep<128,  64,  64><<<1024, 256>>>(W2, wb2);
    wbprep< 64,  32,  32><<< 512, 256>>>(W3, wb3);
    wbprep< 32,  18,  32><<< 256, 256>>>(W4, wb4);

    mconv<512,128,128,true ,0><<<dim3(16, 8), 256, 135168>>>(inT, 0,               wb1, b1, h1);
    mconv<128, 64, 64,true ,0><<<dim3(16, 8), 256, 118784>>>(h1, (size_t)NP * 128, wb2, b2, h2);
    mconv< 64, 32, 32,true ,0><<<dim3(16, 8), 256, 110592>>>(h2, (size_t)NP * 64,  wb3, b3, h3);
    mconv< 32, 32, 18,false,1><<<dim3(16, 8), 256, 110592>>>(h3, (size_t)NP * 32,  wb4, b4, oa);

    warp_kernel<<<NP / 4, 256>>>(oa, garT, mask, out);
}

// round 6
// speedup vs baseline: 5.9234x; 1.7250x over previous
#include <cuda_runtime.h>
#include <cuda_bf16.h>
#include <cuda_fp16.h>
#include <cstdint>
#include <cstddef>

// ---------------------------------------------------------------------------
// DSDModules via mma.sync bf16 m16n8k16 (HMMA; tcgen05 not available through
// the compute_103 virtual arch). v3: bf16 operands (2x K per HMMA, fp32
// accum), ldmatrix.x4 fragments, M=128 tiles with 2 CTAs/SM, band-reuse
// (9x less A traffic), fp16 gather table for the deformable warp stage.
// ---------------------------------------------------------------------------

#define NP 4096

// ---- scratch offsets (float units) -----------------------------------------
#define OFF_INT  0ull            // inTb  [4096][512]  bf16
#define OFF_GART 1048576ull      // garTh [4096][256]  fp16
#define OFF_WB1  1572864ull      // wb1   [8][128][4608] bf16
#define OFF_WB2  3932160ull      // wb2   [8][64][1152]  bf16
#define OFF_WB3  4227072ull      // wb3   [8][32][576]   bf16
#define OFF_WB4  4300800ull      // wb4   [8][32][576]   bf16 (cin-padded)
#define OFF_H1   4374528ull      // h1 [8][4096][128] bf16
#define OFF_H2   6471680ull      // h2 [8][4096][64]  bf16
#define OFF_H3   7520256ull      // h3 [8][4096][64]  bf16 (upper 32 stay 0)
#define OFF_OA   8568832ull      // oa [8][18][4096]  fp32
#define SCRATCH_FLOATS 9158656ull

__device__ __align__(1024) float g_scratch[SCRATCH_FLOATS];

// ---- helpers ---------------------------------------------------------------
__device__ __forceinline__ uint32_t smem_u32(const void* p) {
    uint32_t a;
    asm("{ .reg .u64 t; cvta.to.shared.u64 t, %1; cvt.u32.u64 %0, t; }"
        : "=r"(a) : "l"(p));
    return a;
}
__device__ __forceinline__ void cp16(uint32_t sa, const void* g, bool ok) {
    int sz = ok ? 16 : 0;
    asm volatile("cp.async.cg.shared.global [%0], [%1], 16, %2;"
                 :: "r"(sa), "l"(g), "r"(sz) : "memory");
}
#define CP_COMMIT() asm volatile("cp.async.commit_group;" ::: "memory")
#define CP_WAIT(n)  asm volatile("cp.async.wait_group %0;" :: "n"(n) : "memory")

__device__ __forceinline__ void ldsm4(uint32_t* r, uint32_t addr) {
    asm volatile("ldmatrix.sync.aligned.m8n8.x4.shared.b16 {%0,%1,%2,%3}, [%4];"
                 : "=r"(r[0]), "=r"(r[1]), "=r"(r[2]), "=r"(r[3]) : "r"(addr));
}
__device__ __forceinline__ void mma_bf16(float* c, const uint32_t* a, const uint32_t* b) {
    asm volatile(
        "mma.sync.aligned.m16n8k16.row.col.f32.bf16.bf16.f32 "
        "{%0,%1,%2,%3}, {%4,%5,%6,%7}, {%8,%9}, {%0,%1,%2,%3};"
        : "+f"(c[0]), "+f"(c[1]), "+f"(c[2]), "+f"(c[3])
        : "r"(a[0]), "r"(a[1]), "r"(a[2]), "r"(a[3]), "r"(b[0]), "r"(b[1]));
}

// ---------------------------------------------------------------------------
// concat(gar, cond) [512][4096] -> inTb [4096][512] bf16, garTh [4096][256] fp16
// ---------------------------------------------------------------------------
__global__ void transpose_in(const float* __restrict__ gar,
                             const float* __restrict__ cond,
                             __nv_bfloat16* __restrict__ inTb,
                             __half* __restrict__ garTh) {
    __shared__ float tile[32][33];
    int p0 = blockIdx.x * 32;
    int c0 = blockIdx.y * 32;
    for (int i = threadIdx.y; i < 32; i += 8) {
        int c = c0 + i;
        const float* src = (c < 256) ? (gar + (size_t)c * NP) : (cond + (size_t)(c - 256) * NP);
        tile[i][threadIdx.x] = src[p0 + threadIdx.x];
    }
    __syncthreads();
    for (int i = threadIdx.y; i < 32; i += 8) {
        float v = tile[threadIdx.x][i];
        int pix = p0 + i, c = c0 + threadIdx.x;
        inTb[(size_t)pix * 512 + c] = __float2bfloat16_rn(v);
        if (c0 < 256)
            garTh[(size_t)pix * 256 + c] = __float2half_rn(v);
    }
}

// ---------------------------------------------------------------------------
// W [G][COUT_REAL][CIN_REAL][3][3] -> Wb bf16 [G][COUT_PAD][CIN_PAD*9],
// K = tap*CIN_PAD + cin, zero for cin>=CIN_REAL or m>=COUT_REAL.
// ---------------------------------------------------------------------------
template<int CIN_REAL, int CIN_PAD, int COUT_REAL, int COUT_PAD>
__global__ void wbprep(const float* __restrict__ W, __nv_bfloat16* __restrict__ Wb) {
    constexpr int K = CIN_PAD * 9;
    constexpr size_t total = (size_t)8 * COUT_PAD * K;
    for (size_t i = (size_t)blockIdx.x * blockDim.x + threadIdx.x; i < total;
         i += (size_t)gridDim.x * blockDim.x) {
        int k = (int)(i % K);
        size_t rem = i / K;
        int m = (int)(rem % COUT_PAD);
        int g = (int)(rem / COUT_PAD);
        int tap = k / CIN_PAD, cin = k - tap * CIN_PAD;
        float v = 0.f;
        if (m < COUT_REAL && cin < CIN_REAL)
            v = W[((size_t)(g * COUT_REAL + m) * CIN_REAL + cin) * 9 + tap];
        Wb[i] = __float2bfloat16_rn(v);
    }
}

// ---------------------------------------------------------------------------
// bf16 band-reuse implicit-GEMM 3x3 conv.
//   CTA: 128 px (2 image rows) x COUT, 256 threads (8 warps: 4 M x 2 N),
//   2 CTAs/SM. Band: 4 rows x 66 cols x 64 cin (128B rows), double-buffered,
//   reused by all 9 taps; B tap-chunks (COUT x 64 k) double-buffered.
//   in: [g][4096][CIN] bf16 (gstride elems between groups; 0 => shared).
//   OUT_MODE 0: bf16 out[g][pix][OUT_STRIDE]; OUT_MODE 1: fp32 out[g][m][NP].
// grid (32, 8).
// ---------------------------------------------------------------------------
template<int CIN, int COUT, int COUT_REAL, int OUT_STRIDE, bool RELU, int OUT_MODE>
__global__ __launch_bounds__(256, 2)
void mconv(const __nv_bfloat16* __restrict__ in, size_t gstride,
           const __nv_bfloat16* __restrict__ Wb, const float* __restrict__ bias,
           void* __restrict__ outv) {
    constexpr int K      = CIN * 9;
    constexpr int NCC    = CIN / 64;
    constexpr int TOT    = NCC * 9;
    constexpr int WN     = COUT / 2;
    constexpr int NTT    = WN / 8;
    constexpr int BPIX   = 264;                // 4 rows x 66 cols
    constexpr int BSTAGE = BPIX * 128;         // bytes (64 cin x 2B per row)
    constexpr int BBS    = COUT * 128;         // B stage bytes

    extern __shared__ char sm[];
    uint32_t dyn  = smem_u32(sm);
    uint32_t base = (dyn + 1023u) & ~1023u;

    const int tid  = threadIdx.x;
    const int warp = tid >> 5;
    const int lane = tid & 31;
    const int lq   = lane >> 2;
    const int lc   = lane & 3;
    const int wm   = warp & 3;
    const int wn   = warp >> 2;
    const int tile = blockIdx.x;
    const int g    = blockIdx.y;
    const int y0   = tile * 2 - 1;

    const __nv_bfloat16* src = in + (size_t)g * gstride;
    const __nv_bfloat16* wg  = Wb + (size_t)g * COUT * K;

    uint32_t bandA[2] = { base, base + BSTAGE };
    uint32_t bbA[2]   = { base + 2 * BSTAGE, base + 2 * BSTAGE + BBS };

    float acc[2][NTT][4];
    #pragma unroll
    for (int i = 0; i < 2; i++)
        #pragma unroll
        for (int j = 0; j < NTT; j++)
            #pragma unroll
            for (int q = 0; q < 4; q++) acc[i][j][q] = 0.f;

    auto band_load = [&](int cc, int buf) {
        int c0 = cc * 64;
        for (int it = tid; it < BPIX * 8; it += 256) {
            int bp = it >> 3, seg = it & 7;
            int br = bp / 66;
            int col = bp - br * 66;
            int y = y0 + br, x = col - 1;
            bool ok = ((unsigned)y < 64u) & ((unsigned)x < 64u);
            int pix = ok ? (y * 64 + x) : 0;
            const __nv_bfloat16* gp = src + (size_t)pix * CIN + c0 + seg * 8;
            cp16(bandA[buf] + (uint32_t)(bp * 128 + ((seg * 16) ^ ((bp & 7) * 16))), gp, ok);
        }
    };
    auto b_load = [&](int kc, int buf) {
        int cc = kc / 9;
        int koff = (kc - cc * 9) * CIN + cc * 64;
        for (int it = tid; it < COUT * 8; it += 256) {
            int m = it >> 3, seg = it & 7;
            const __nv_bfloat16* gp = wg + (size_t)m * K + koff + seg * 8;
            cp16(bbA[buf] + (uint32_t)(m * 128 + ((seg * 16) ^ ((m & 7) * 16))), gp, true);
        }
    };

    // lane-constant ldmatrix address components
    const int amat  = lane >> 3;                       // 0..3
    const int aroff = (lane & 7) + (amat & 1) * 8;     // row within 16-row tile
    const int akb   = (amat >> 1) * 16;                // k-lo / k-hi bytes

    auto compute = [&](int tap, int bandbuf, int bbuf) {
        int r = tap / 3, s = tap - 3 * (tap / 3);
        int brow = (wm >> 1) + r;
        int bcol = (wm & 1) * 32 + s;
        int bbase0 = brow * 66 + bcol;
        uint32_t aS = bandA[bandbuf];
        uint32_t bS = bbA[bbuf];
        #pragma unroll
        for (int seg = 0; seg < 4; seg++) {
            uint32_t af[2][4];
            #pragma unroll
            for (int mt = 0; mt < 2; mt++) {
                int bp = bbase0 + mt * 16 + aroff;
                uint32_t addr = aS + (uint32_t)(bp * 128 + ((seg * 32 + akb) ^ ((bp & 7) * 16)));
                ldsm4(af[mt], addr);
            }
            uint32_t bf[NTT][2];
            #pragma unroll
            for (int ntp = 0; ntp < NTT / 2; ntp++) {
                int n = wn * WN + (ntp * 2 + (lane >> 4)) * 8 + (lane & 7);
                int kb = ((lane >> 3) & 1) * 16;
                uint32_t addr = bS + (uint32_t)(n * 128 + ((seg * 32 + kb) ^ ((n & 7) * 16)));
                uint32_t tmp[4];
                ldsm4(tmp, addr);
                bf[2 * ntp][0] = tmp[0]; bf[2 * ntp][1] = tmp[1];
                bf[2 * ntp + 1][0] = tmp[2]; bf[2 * ntp + 1][1] = tmp[3];
            }
            #pragma unroll
            for (int mt = 0; mt < 2; mt++)
                #pragma unroll
                for (int nt = 0; nt < NTT; nt++)
                    mma_bf16(acc[mt][nt], af[mt], bf[nt]);
        }
    };

    band_load(0, 0); CP_COMMIT();
    b_load(0, 0);    CP_COMMIT();

    for (int kc = 0; kc < TOT; kc++) {
        int cc  = kc / 9;
        int tap = kc - cc * 9;
        if (tap == 8 && cc + 1 < NCC) {
            band_load(cc + 1, (cc + 1) & 1); CP_COMMIT();
            b_load(kc + 1, (kc + 1) & 1);    CP_COMMIT();
            CP_WAIT(2);
        } else if (kc + 1 < TOT) {
            b_load(kc + 1, (kc + 1) & 1);    CP_COMMIT();
            CP_WAIT(1);
        } else {
            CP_WAIT(0);
        }
        __syncthreads();
        compute(tap, cc & 1, kc & 1);
        __syncthreads();
    }

    // Epilogue: bias + lrelu, store.
    #pragma unroll
    for (int mt = 0; mt < 2; mt++) {
        int prow = tile * 128 + wm * 32 + mt * 16 + lq;
        #pragma unroll
        for (int nt = 0; nt < NTT; nt++) {
            int n0 = wn * WN + nt * 8 + lc * 2;
            float b0 = (n0     < COUT_REAL) ? bias[g * COUT_REAL + n0]     : 0.f;
            float b1 = (n0 + 1 < COUT_REAL) ? bias[g * COUT_REAL + n0 + 1] : 0.f;
            #pragma unroll
            for (int h = 0; h < 2; h++) {
                int p = prow + h * 8;
                float v0 = acc[mt][nt][h * 2]     + b0;
                float v1 = acc[mt][nt][h * 2 + 1] + b1;
                if (RELU) {
                    v0 = (v0 >= 0.f) ? v0 : 0.1f * v0;
                    v1 = (v1 >= 0.f) ? v1 : 0.1f * v1;
                }
                if (OUT_MODE == 0) {
                    __nv_bfloat16* ob = (__nv_bfloat16*)outv;
                    __nv_bfloat162 pr;
                    pr.x = __float2bfloat16_rn(v0);
                    pr.y = __float2bfloat16_rn(v1);
                    *(__nv_bfloat162*)(ob + ((size_t)g * NP + p) * OUT_STRIDE + n0) = pr;
                } else {
                    float* of = (float*)outv;
                    if (n0 < COUT_REAL)
                        of[(size_t)(g * COUT_REAL + n0) * NP + p] = v0;
                    if (n0 + 1 < COUT_REAL)
                        of[(size_t)(g * COUT_REAL + n0 + 1) * NP + p] = v1;
                }
            }
        }
    }
}

// ---------------------------------------------------------------------------
// Final warp/sample kernel. oa [G][18][NP] fp32; gathers garTh [4096][256] fp16.
// ---------------------------------------------------------------------------
__global__ __launch_bounds__(256)
void warp_kernel(const float* __restrict__ oa, const __half* __restrict__ garTh,
                 const float* __restrict__ mask, float* __restrict__ out) {
    __shared__ int   sO[4][192];
    __shared__ float sA[4][192];

    const int pix0 = blockIdx.x * 4;
    const int tt = threadIdx.x;

    if (tt < 24) {
        int p = tt / 6, k = tt - (tt / 6) * 6;
        int pix = pix0 + p;
        float fx = (float)(pix & 63);
        float fy = (float)(pix >> 6);
        float lg[8], ox[8], oy[8];
        #pragma unroll
        for (int g = 0; g < 8; g++) {
            const float* base = oa + (size_t)g * 18 * NP + pix;
            lg[g] = base[(12 + k) * NP];
            ox[g] = base[(2 * k) * NP];
            oy[g] = base[(2 * k + 1) * NP];
        }
        float m = lg[0];
        #pragma unroll
        for (int g = 1; g < 8; g++) m = fmaxf(m, lg[g]);
        float s = 0.f;
        #pragma unroll
        for (int g = 0; g < 8; g++) { lg[g] = expf(lg[g] - m); s += lg[g]; }
        float inv = 1.f / s;
        #pragma unroll
        for (int g = 0; g < 8; g++) {
            float attn = lg[g] * inv;
            float xs = fminf(fmaxf((fx + ox[g]) * (64.0f / 63.0f) - 0.5f, 0.f), 63.f);
            float ys = fminf(fmaxf((fy + oy[g]) * (64.0f / 63.0f) - 0.5f, 0.f), 63.f);
            float x0f = floorf(xs), y0f = floorf(ys);
            float wx = xs - x0f, wy = ys - y0f;
            int x0 = (int)x0f, y0 = (int)y0f;
            int x1 = min(x0 + 1, 63), y1 = min(y0 + 1, 63);
            int q = (p * 6 + k) * 8 + g;
            sO[0][q] = (y0 * 64 + x0) * 256;
            sO[1][q] = (y0 * 64 + x1) * 256;
            sO[2][q] = (y1 * 64 + x0) * 256;
            sO[3][q] = (y1 * 64 + x1) * 256;
            sA[0][q] = attn * (1.f - wy) * (1.f - wx);
            sA[1][q] = attn * (1.f - wy) * wx;
            sA[2][q] = attn * wy * (1.f - wx);
            sA[3][q] = attn * wy * wx;
        }
    }
    __syncthreads();

    const int c = tt;  // channel
    float mk[8];
    #pragma unroll
    for (int g = 0; g < 8; g++) mk[g] = mask[g * 256 + c];

    for (int p = 0; p < 4; p++) {
        float accP = 0.f;
        for (int g = 0; g < 8; g++) {
            float accG = 0.f;
            #pragma unroll
            for (int k = 0; k < 6; k++) {
                int q = (p * 6 + k) * 8 + g;
                accG += sA[0][q] * __half2float(garTh[sO[0][q] + c])
                      + sA[1][q] * __half2float(garTh[sO[1][q] + c])
                      + sA[2][q] * __half2float(garTh[sO[2][q] + c])
                      + sA[3][q] * __half2float(garTh[sO[3][q] + c]);
            }
            accP += accG * mk[g];
        }
        out[(size_t)c * NP + pix0 + p] = accP;
    }
}

// ---------------------------------------------------------------------------
extern "C" void kernel_launch(void* const* d_in, const int* in_sizes, int n_in,
                              void* d_out, int out_size) {
    const float* gar  = (const float*)d_in[0];
    const float* cond = (const float*)d_in[1];
    const float* mask = (const float*)d_in[2];
    const float* W1   = (const float*)d_in[3];
    const float* b1   = (const float*)d_in[4];
    const float* W2   = (const float*)d_in[5];
    const float* b2   = (const float*)d_in[6];
    const float* W3   = (const float*)d_in[7];
    const float* b3   = (const float*)d_in[8];
    const float* W4   = (const float*)d_in[9];
    const float* b4   = (const float*)d_in[10];
    float* out = (float*)d_out;

    float* S = nullptr;
    cudaGetSymbolAddress((void**)&S, g_scratch);
    __nv_bfloat16* inTb  = (__nv_bfloat16*)(S + OFF_INT);
    __half*        garTh = (__half*)       (S + OFF_GART);
    __nv_bfloat16* wb1   = (__nv_bfloat16*)(S + OFF_WB1);
    __nv_bfloat16* wb2   = (__nv_bfloat16*)(S + OFF_WB2);
    __nv_bfloat16* wb3   = (__nv_bfloat16*)(S + OFF_WB3);
    __nv_bfloat16* wb4   = (__nv_bfloat16*)(S + OFF_WB4);
    __nv_bfloat16* h1    = (__nv_bfloat16*)(S + OFF_H1);
    __nv_bfloat16* h2    = (__nv_bfloat16*)(S + OFF_H2);
    __nv_bfloat16* h3    = (__nv_bfloat16*)(S + OFF_H3);
    float*         oa    = S + OFF_OA;

    // dynamic smem: 2*band + 2*B  (+1KB align slack)
    const int SM1 = 2 * 264 * 128 + 2 * 128 * 128 + 1024;  // 101376
    const int SM2 = 2 * 264 * 128 + 2 * 64 * 128 + 1024;   //  84992
    const int SM3 = 2 * 264 * 128 + 2 * 32 * 128 + 1024;   //  76800

    cudaFuncSetAttribute(mconv<512,128,128,128,true ,0>, cudaFuncAttributeMaxDynamicSharedMemorySize, SM1);
    cudaFuncSetAttribute(mconv<128, 64, 64, 64,true ,0>, cudaFuncAttributeMaxDynamicSharedMemorySize, SM2);
    cudaFuncSetAttribute(mconv< 64, 32, 32, 64,true ,0>, cudaFuncAttributeMaxDynamicSharedMemorySize, SM3);
    cudaFuncSetAttribute(mconv< 64, 32, 18,  1,false,1>, cudaFuncAttributeMaxDynamicSharedMemorySize, SM3);

    transpose_in<<<dim3(128, 16), dim3(32, 8)>>>(gar, cond, inTb, garTh);
    wbprep<512, 512, 128, 128><<<4096, 256>>>(W1, wb1);
    wbprep<128, 128,  64,  64><<<1024, 256>>>(W2, wb2);
    wbprep< 64,  64,  32,  32><<< 512, 256>>>(W3, wb3);
    wbprep< 32,  64,  18,  32><<< 512, 256>>>(W4, wb4);

    mconv<512,128,128,128,true ,0><<<dim3(32, 8), 256, SM1>>>(inTb, 0,               wb1, b1, h1);
    mconv<128, 64, 64, 64,true ,0><<<dim3(32, 8), 256, SM2>>>(h1, (size_t)NP * 128,  wb2, b2, h2);
    mconv< 64, 32, 32, 64,true ,0><<<dim3(32, 8), 256, SM3>>>(h2, (size_t)NP * 64,   wb3, b3, h3);
    mconv< 64, 32, 18,  1,false,1><<<dim3(32, 8), 256, SM3>>>(h3, (size_t)NP * 64,   wb4, b4, oa);

    warp_kernel<<<NP / 4, 256>>>(oa, garTh, mask, out);
}

// round 7
// speedup vs baseline: 6.4418x; 1.0875x over previous
#include <cuda_runtime.h>
#include <cuda_bf16.h>
#include <cuda_fp16.h>
#include <cstdint>
#include <cstddef>

// ---------------------------------------------------------------------------
// DSDModules via mma.sync bf16 m16n8k16 (HMMA; tcgen05 not reachable through
// the compute_103 virtual arch). v4: 4-warp CTAs with 64x64 warp tiles
// (crossbar traffic -33%, 2x compute per barrier), fused prep kernel,
// band-reuse implicit GEMM, fp16 gather table for the deformable warp.
// ---------------------------------------------------------------------------

#define NP 4096

// ---- scratch offsets (float units) -----------------------------------------
#define OFF_INT  0ull            // inTb  [4096][512]  bf16
#define OFF_GART 1048576ull      // garTh [4096][256]  fp16
#define OFF_WB1  1572864ull      // wb1   [8][128][4608] bf16
#define OFF_WB2  3932160ull      // wb2   [8][64][1152]  bf16
#define OFF_WB3  4227072ull      // wb3   [8][32][576]   bf16
#define OFF_WB4  4300800ull      // wb4   [8][32][576]   bf16 (cin-padded)
#define OFF_H1   4374528ull      // h1 [8][4096][128] bf16
#define OFF_H2   6471680ull      // h2 [8][4096][64]  bf16
#define OFF_H3   7520256ull      // h3 [8][4096][64]  bf16 (upper 32 stay 0)
#define OFF_OA   8568832ull      // oa [8][18][4096]  fp32
#define SCRATCH_FLOATS 9158656ull

__device__ __align__(1024) float g_scratch[SCRATCH_FLOATS];

// ---- helpers ---------------------------------------------------------------
__device__ __forceinline__ uint32_t smem_u32(const void* p) {
    uint32_t a;
    asm("{ .reg .u64 t; cvta.to.shared.u64 t, %1; cvt.u32.u64 %0, t; }"
        : "=r"(a) : "l"(p));
    return a;
}
__device__ __forceinline__ void cp16(uint32_t sa, const void* g, bool ok) {
    int sz = ok ? 16 : 0;
    asm volatile("cp.async.cg.shared.global [%0], [%1], 16, %2;"
                 :: "r"(sa), "l"(g), "r"(sz) : "memory");
}
#define CP_COMMIT() asm volatile("cp.async.commit_group;" ::: "memory")
#define CP_WAIT(n)  asm volatile("cp.async.wait_group %0;" :: "n"(n) : "memory")

__device__ __forceinline__ void ldsm4(uint32_t* r, uint32_t addr) {
    asm volatile("ldmatrix.sync.aligned.m8n8.x4.shared.b16 {%0,%1,%2,%3}, [%4];"
                 : "=r"(r[0]), "=r"(r[1]), "=r"(r[2]), "=r"(r[3]) : "r"(addr));
}
__device__ __forceinline__ void mma_bf16(float* c, const uint32_t* a, const uint32_t* b) {
    asm volatile(
        "mma.sync.aligned.m16n8k16.row.col.f32.bf16.bf16.f32 "
        "{%0,%1,%2,%3}, {%4,%5,%6,%7}, {%8,%9}, {%0,%1,%2,%3};"
        : "+f"(c[0]), "+f"(c[1]), "+f"(c[2]), "+f"(c[3])
        : "r"(a[0]), "r"(a[1]), "r"(a[2]), "r"(a[3]), "r"(b[0]), "r"(b[1]));
}

// ---------------------------------------------------------------------------
// Fused prep kernel.
//   Blocks [0, 2048):        transpose concat(gar,cond) -> inTb bf16 + garTh fp16
//   Blocks [2048, 2048+2752): all 4 weight reorders (grid-stride per region)
// ---------------------------------------------------------------------------
__device__ void wb_region(const float* __restrict__ W, __nv_bfloat16* __restrict__ Wb,
                          int CINR, int CINP, int COUTR, int COUTP,
                          size_t tidg, size_t nthreads) {
    int K = CINP * 9;
    size_t total = (size_t)8 * COUTP * K;
    for (size_t i = tidg; i < total; i += nthreads) {
        int k = (int)(i % K);
        size_t rem = i / K;
        int m = (int)(rem % COUTP);
        int g = (int)(rem / COUTP);
        int tap = k / CINP, cin = k - tap * CINP;
        float v = 0.f;
        if (m < COUTR && cin < CINR)
            v = W[((size_t)(g * COUTR + m) * CINR + cin) * 9 + tap];
        Wb[i] = __float2bfloat16_rn(v);
    }
}

__global__ __launch_bounds__(256)
void prep_all(const float* __restrict__ gar, const float* __restrict__ cond,
              __nv_bfloat16* __restrict__ inTb, __half* __restrict__ garTh,
              const float* __restrict__ W1, __nv_bfloat16* __restrict__ wb1,
              const float* __restrict__ W2, __nv_bfloat16* __restrict__ wb2,
              const float* __restrict__ W3, __nv_bfloat16* __restrict__ wb3,
              const float* __restrict__ W4, __nv_bfloat16* __restrict__ wb4) {
    if (blockIdx.x < 2048) {
        __shared__ float tile[32][33];
        int tx = threadIdx.x & 31;
        int ty = threadIdx.x >> 5;
        int p0 = (blockIdx.x & 127) * 32;
        int c0 = (blockIdx.x >> 7) * 32;
        for (int i = ty; i < 32; i += 8) {
            int c = c0 + i;
            const float* src = (c < 256) ? (gar + (size_t)c * NP)
                                         : (cond + (size_t)(c - 256) * NP);
            tile[i][tx] = src[p0 + tx];
        }
        __syncthreads();
        for (int i = ty; i < 32; i += 8) {
            float v = tile[tx][i];
            int pix = p0 + i, c = c0 + tx;
            inTb[(size_t)pix * 512 + c] = __float2bfloat16_rn(v);
            if (c0 < 256)
                garTh[(size_t)pix * 256 + c] = __float2half_rn(v);
        }
    } else {
        size_t tidg = (size_t)(blockIdx.x - 2048) * 256 + threadIdx.x;
        size_t nt   = (size_t)2752 * 256;
        wb_region(W1, wb1, 512, 512, 128, 128, tidg, nt);
        wb_region(W2, wb2, 128, 128,  64,  64, tidg, nt);
        wb_region(W3, wb3,  64,  64,  32,  32, tidg, nt);
        wb_region(W4, wb4,  32,  64,  18,  32, tidg, nt);
    }
}

// ---------------------------------------------------------------------------
// bf16 band-reuse implicit-GEMM 3x3 conv.
//   CTA: 128 px (2 image rows) x COUT, 128 threads (4 warps: 2 M x 2 N,
//   64x64 tiles), 2 CTAs/SM. Band: 4 rows x 66 cols x 64 cin (128B rows),
//   double-buffered, reused by 9 taps; B tap-chunks double-buffered.
//   in: [g][4096][CIN] bf16 (gstride elems between groups; 0 => shared).
//   OUT_MODE 0: bf16 out[g][pix][OUT_STRIDE]; OUT_MODE 1: fp32 out[g][m][NP].
// grid (32, 8).
// ---------------------------------------------------------------------------
template<int CIN, int COUT, int COUT_REAL, int OUT_STRIDE, bool RELU, int OUT_MODE>
__global__ __launch_bounds__(128, 2)
void mconv(const __nv_bfloat16* __restrict__ in, size_t gstride,
           const __nv_bfloat16* __restrict__ Wb, const float* __restrict__ bias,
           void* __restrict__ outv) {
    constexpr int K      = CIN * 9;
    constexpr int NCC    = CIN / 64;
    constexpr int TOT    = NCC * 9;
    constexpr int WN     = COUT / 2;
    constexpr int NTT    = WN / 8;
    constexpr int BPIX   = 264;                // 4 rows x 66 cols
    constexpr int BSTAGE = BPIX * 128;         // bytes (64 cin x 2B per row)
    constexpr int BBS    = COUT * 128;         // B stage bytes

    extern __shared__ char sm[];
    uint32_t dyn  = smem_u32(sm);
    uint32_t base = (dyn + 1023u) & ~1023u;

    const int tid  = threadIdx.x;
    const int warp = tid >> 5;
    const int lane = tid & 31;
    const int lq   = lane >> 2;
    const int lc   = lane & 3;
    const int wm   = warp & 1;                 // image row within tile
    const int wn   = warp >> 1;                // N half
    const int tile = blockIdx.x;
    const int g    = blockIdx.y;
    const int y0   = tile * 2 - 1;

    const __nv_bfloat16* src = in + (size_t)g * gstride;
    const __nv_bfloat16* wg  = Wb + (size_t)g * COUT * K;

    uint32_t bandA[2] = { base, base + BSTAGE };
    uint32_t bbA[2]   = { base + 2 * BSTAGE, base + 2 * BSTAGE + BBS };

    float acc[4][NTT][4];
    #pragma unroll
    for (int i = 0; i < 4; i++)
        #pragma unroll
        for (int j = 0; j < NTT; j++)
            #pragma unroll
            for (int q = 0; q < 4; q++) acc[i][j][q] = 0.f;

    auto band_load = [&](int cc, int buf) {
        int c0 = cc * 64;
        for (int it = tid; it < BPIX * 8; it += 128) {
            int bp = it >> 3, seg = it & 7;
            int br = bp / 66;
            int col = bp - br * 66;
            int y = y0 + br, x = col - 1;
            bool ok = ((unsigned)y < 64u) & ((unsigned)x < 64u);
            int pix = ok ? (y * 64 + x) : 0;
            const __nv_bfloat16* gp = src + (size_t)pix * CIN + c0 + seg * 8;
            cp16(bandA[buf] + (uint32_t)(bp * 128 + ((seg * 16) ^ ((bp & 7) * 16))), gp, ok);
        }
    };
    auto b_load = [&](int kc, int buf) {
        int cc = kc / 9;
        int koff = (kc - cc * 9) * CIN + cc * 64;
        for (int it = tid; it < COUT * 8; it += 128) {
            int m = it >> 3, seg = it & 7;
            const __nv_bfloat16* gp = wg + (size_t)m * K + koff + seg * 8;
            cp16(bbA[buf] + (uint32_t)(m * 128 + ((seg * 16) ^ ((m & 7) * 16))), gp, true);
        }
    };

    // lane-constant ldmatrix address components (A fragments)
    const int amat  = lane >> 3;                       // 0..3
    const int aroff = (lane & 7) + (amat & 1) * 8;     // row within 16-row tile
    const int akb   = (amat >> 1) * 16;                // k-lo / k-hi bytes

    auto compute = [&](int tap, int bandbuf, int bbuf) {
        int r = tap / 3, s = tap - 3 * (tap / 3);
        int bbase0 = (wm + r) * 66 + s;
        uint32_t aS = bandA[bandbuf];
        uint32_t bS = bbA[bbuf];
        #pragma unroll
        for (int seg = 0; seg < 4; seg++) {
            uint32_t af[4][4];
            #pragma unroll
            for (int mt = 0; mt < 4; mt++) {
                int bp = bbase0 + mt * 16 + aroff;
                uint32_t addr = aS + (uint32_t)(bp * 128 + ((seg * 32 + akb) ^ ((bp & 7) * 16)));
                ldsm4(af[mt], addr);
            }
            uint32_t bf[NTT][2];
            #pragma unroll
            for (int ntp = 0; ntp < NTT / 2; ntp++) {
                int n = wn * WN + (ntp * 2 + (lane >> 4)) * 8 + (lane & 7);
                int kb = ((lane >> 3) & 1) * 16;
                uint32_t addr = bS + (uint32_t)(n * 128 + ((seg * 32 + kb) ^ ((n & 7) * 16)));
                uint32_t tmp[4];
                ldsm4(tmp, addr);
                bf[2 * ntp][0] = tmp[0]; bf[2 * ntp][1] = tmp[1];
                bf[2 * ntp + 1][0] = tmp[2]; bf[2 * ntp + 1][1] = tmp[3];
            }
            #pragma unroll
            for (int mt = 0; mt < 4; mt++)
                #pragma unroll
                for (int nt = 0; nt < NTT; nt++)
                    mma_bf16(acc[mt][nt], af[mt], bf[nt]);
        }
    };

    band_load(0, 0); CP_COMMIT();
    b_load(0, 0);    CP_COMMIT();

    for (int kc = 0; kc < TOT; kc++) {
        int cc  = kc / 9;
        int tap = kc - cc * 9;
        if (tap == 8 && cc + 1 < NCC) {
            band_load(cc + 1, (cc + 1) & 1); CP_COMMIT();
            b_load(kc + 1, (kc + 1) & 1);    CP_COMMIT();
            CP_WAIT(2);
        } else if (kc + 1 < TOT) {
            b_load(kc + 1, (kc + 1) & 1);    CP_COMMIT();
            CP_WAIT(1);
        } else {
            CP_WAIT(0);
        }
        __syncthreads();
        compute(tap, cc & 1, kc & 1);
        __syncthreads();
    }

    // Epilogue: bias + lrelu, store.
    #pragma unroll
    for (int mt = 0; mt < 4; mt++) {
        int prow = tile * 128 + wm * 64 + mt * 16 + lq;
        #pragma unroll
        for (int nt = 0; nt < NTT; nt++) {
            int n0 = wn * WN + nt * 8 + lc * 2;
            float b0 = (n0     < COUT_REAL) ? bias[g * COUT_REAL + n0]     : 0.f;
            float b1 = (n0 + 1 < COUT_REAL) ? bias[g * COUT_REAL + n0 + 1] : 0.f;
            #pragma unroll
            for (int h = 0; h < 2; h++) {
                int p = prow + h * 8;
                float v0 = acc[mt][nt][h * 2]     + b0;
                float v1 = acc[mt][nt][h * 2 + 1] + b1;
                if (RELU) {
                    v0 = (v0 >= 0.f) ? v0 : 0.1f * v0;
                    v1 = (v1 >= 0.f) ? v1 : 0.1f * v1;
                }
                if (OUT_MODE == 0) {
                    __nv_bfloat16* ob = (__nv_bfloat16*)outv;
                    __nv_bfloat162 pr;
                    pr.x = __float2bfloat16_rn(v0);
                    pr.y = __float2bfloat16_rn(v1);
                    *(__nv_bfloat162*)(ob + ((size_t)g * NP + p) * OUT_STRIDE + n0) = pr;
                } else {
                    float* of = (float*)outv;
                    if (n0 < COUT_REAL)
                        of[(size_t)(g * COUT_REAL + n0) * NP + p] = v0;
                    if (n0 + 1 < COUT_REAL)
                        of[(size_t)(g * COUT_REAL + n0 + 1) * NP + p] = v1;
                }
            }
        }
    }
}

// ---------------------------------------------------------------------------
// Final warp/sample kernel. oa [G][18][NP] fp32; gathers garTh [4096][256] fp16.
// ---------------------------------------------------------------------------
__global__ __launch_bounds__(256)
void warp_kernel(const float* __restrict__ oa, const __half* __restrict__ garTh,
                 const float* __restrict__ mask, float* __restrict__ out) {
    __shared__ int   sO[4][192];
    __shared__ float sA[4][192];

    const int pix0 = blockIdx.x * 4;
    const int tt = threadIdx.x;

    if (tt < 24) {
        int p = tt / 6, k = tt - (tt / 6) * 6;
        int pix = pix0 + p;
        float fx = (float)(pix & 63);
        float fy = (float)(pix >> 6);
        float lg[8], ox[8], oy[8];
        #pragma unroll
        for (int g = 0; g < 8; g++) {
            const float* base = oa + (size_t)g * 18 * NP + pix;
            lg[g] = base[(12 + k) * NP];
            ox[g] = base[(2 * k) * NP];
            oy[g] = base[(2 * k + 1) * NP];
        }
        float m = lg[0];
        #pragma unroll
        for (int g = 1; g < 8; g++) m = fmaxf(m, lg[g]);
        float s = 0.f;
        #pragma unroll
        for (int g = 0; g < 8; g++) { lg[g] = expf(lg[g] - m); s += lg[g]; }
        float inv = 1.f / s;
        #pragma unroll
        for (int g = 0; g < 8; g++) {
            float attn = lg[g] * inv;
            float xs = fminf(fmaxf((fx + ox[g]) * (64.0f / 63.0f) - 0.5f, 0.f), 63.f);
            float ys = fminf(fmaxf((fy + oy[g]) * (64.0f / 63.0f) - 0.5f, 0.f), 63.f);
            float x0f = floorf(xs), y0f = floorf(ys);
            float wx = xs - x0f, wy = ys - y0f;
            int x0 = (int)x0f, y0 = (int)y0f;
            int x1 = min(x0 + 1, 63), y1 = min(y0 + 1, 63);
            int q = (p * 6 + k) * 8 + g;
            sO[0][q] = (y0 * 64 + x0) * 256;
            sO[1][q] = (y0 * 64 + x1) * 256;
            sO[2][q] = (y1 * 64 + x0) * 256;
            sO[3][q] = (y1 * 64 + x1) * 256;
            sA[0][q] = attn * (1.f - wy) * (1.f - wx);
            sA[1][q] = attn * (1.f - wy) * wx;
            sA[2][q] = attn * wy * (1.f - wx);
            sA[3][q] = attn * wy * wx;
        }
    }
    __syncthreads();

    const int c = tt;  // channel
    float mk[8];
    #pragma unroll
    for (int g = 0; g < 8; g++) mk[g] = mask[g * 256 + c];

    for (int p = 0; p < 4; p++) {
        float accP = 0.f;
        for (int g = 0; g < 8; g++) {
            float accG = 0.f;
            #pragma unroll
            for (int k = 0; k < 6; k++) {
                int q = (p * 6 + k) * 8 + g;
                accG += sA[0][q] * __half2float(garTh[sO[0][q] + c])
                      + sA[1][q] * __half2float(garTh[sO[1][q] + c])
                      + sA[2][q] * __half2float(garTh[sO[2][q] + c])
                      + sA[3][q] * __half2float(garTh[sO[3][q] + c]);
            }
            accP += accG * mk[g];
        }
        out[(size_t)c * NP + pix0 + p] = accP;
    }
}

// ---------------------------------------------------------------------------
extern "C" void kernel_launch(void* const* d_in, const int* in_sizes, int n_in,
                              void* d_out, int out_size) {
    const float* gar  = (const float*)d_in[0];
    const float* cond = (const float*)d_in[1];
    const float* mask = (const float*)d_in[2];
    const float* W1   = (const float*)d_in[3];
    const float* b1   = (const float*)d_in[4];
    const float* W2   = (const float*)d_in[5];
    const float* b2   = (const float*)d_in[6];
    const float* W3   = (const float*)d_in[7];
    const float* b3   = (const float*)d_in[8];
    const float* W4   = (const float*)d_in[9];
    const float* b4   = (const float*)d_in[10];
    float* out = (float*)d_out;

    float* S = nullptr;
    cudaGetSymbolAddress((void**)&S, g_scratch);
    __nv_bfloat16* inTb  = (__nv_bfloat16*)(S + OFF_INT);
    __half*        garTh = (__half*)       (S + OFF_GART);
    __nv_bfloat16* wb1   = (__nv_bfloat16*)(S + OFF_WB1);
    __nv_bfloat16* wb2   = (__nv_bfloat16*)(S + OFF_WB2);
    __nv_bfloat16* wb3   = (__nv_bfloat16*)(S + OFF_WB3);
    __nv_bfloat16* wb4   = (__nv_bfloat16*)(S + OFF_WB4);
    __nv_bfloat16* h1    = (__nv_bfloat16*)(S + OFF_H1);
    __nv_bfloat16* h2    = (__nv_bfloat16*)(S + OFF_H2);
    __nv_bfloat16* h3    = (__nv_bfloat16*)(S + OFF_H3);
    float*         oa    = S + OFF_OA;

    // dynamic smem: 2*band + 2*B  (+1KB align slack)
    const int SM1 = 2 * 264 * 128 + 2 * 128 * 128 + 1024;  // 101376
    const int SM2 = 2 * 264 * 128 + 2 * 64 * 128 + 1024;   //  84992
    const int SM3 = 2 * 264 * 128 + 2 * 32 * 128 + 1024;   //  76800

    cudaFuncSetAttribute(mconv<512,128,128,128,true ,0>, cudaFuncAttributeMaxDynamicSharedMemorySize, SM1);
    cudaFuncSetAttribute(mconv<128, 64, 64, 64,true ,0>, cudaFuncAttributeMaxDynamicSharedMemorySize, SM2);
    cudaFuncSetAttribute(mconv< 64, 32, 32, 64,true ,0>, cudaFuncAttributeMaxDynamicSharedMemorySize, SM3);
    cudaFuncSetAttribute(mconv< 64, 32, 18,  1,false,1>, cudaFuncAttributeMaxDynamicSharedMemorySize, SM3);

    prep_all<<<2048 + 2752, 256>>>(gar, cond, inTb, garTh,
                                   W1, wb1, W2, wb2, W3, wb3, W4, wb4);

    mconv<512,128,128,128,true ,0><<<dim3(32, 8), 128, SM1>>>(inTb, 0,               wb1, b1, h1);
    mconv<128, 64, 64, 64,true ,0><<<dim3(32, 8), 128, SM2>>>(h1, (size_t)NP * 128,  wb2, b2, h2);
    mconv< 64, 32, 32, 64,true ,0><<<dim3(32, 8), 128, SM3>>>(h2, (size_t)NP * 64,   wb3, b3, h3);
    mconv< 64, 32, 18,  1,false,1><<<dim3(32, 8), 128, SM3>>>(h3, (size_t)NP * 64,   wb4, b4, oa);

    warp_kernel<<<NP / 4, 256>>>(oa, garTh, mask, out);
}

// round 8
// speedup vs baseline: 8.0454x; 1.2489x over previous
#include <cuda_runtime.h>
#include <cuda_bf16.h>
#include <cuda_fp16.h>
#include <cstdint>
#include <cstddef>

// ---------------------------------------------------------------------------
// DSDModules via mma.sync bf16 m16n8k16. v5: single-sync multistage conv
// loops (1 barrier/chunk, loads overlap MMA), fully-preloaded B + 3 CTAs/SM
// for the CIN=64 convs (zero in-loop barriers), tap-dedup gather in the
// deformable warp stage (exact; collapses colliding bilinear taps).
// ---------------------------------------------------------------------------

#define NP 4096

// ---- scratch offsets (float units) -----------------------------------------
#define OFF_INT  0ull            // inTb  [4096][512]  bf16
#define OFF_GART 1048576ull      // garTh [4096][256]  fp16
#define OFF_WB1  1572864ull      // wb1   [8][128][4608] bf16
#define OFF_WB2  3932160ull      // wb2   [8][64][1152]  bf16
#define OFF_WB3  4227072ull      // wb3   [8][32][576]   bf16
#define OFF_WB4  4300800ull      // wb4   [8][32][576]   bf16 (cin-padded)
#define OFF_H1   4374528ull      // h1 [8][4096][128] bf16
#define OFF_H2   6471680ull      // h2 [8][4096][64]  bf16
#define OFF_H3   7520256ull      // h3 [8][4096][64]  bf16 (upper 32 stay 0)
#define OFF_OA   8568832ull      // oa [8][18][4096]  fp32
#define SCRATCH_FLOATS 9158656ull

__device__ __align__(1024) float g_scratch[SCRATCH_FLOATS];

// ---- helpers ---------------------------------------------------------------
__device__ __forceinline__ uint32_t smem_u32(const void* p) {
    uint32_t a;
    asm("{ .reg .u64 t; cvta.to.shared.u64 t, %1; cvt.u32.u64 %0, t; }"
        : "=r"(a) : "l"(p));
    return a;
}
__device__ __forceinline__ void cp16(uint32_t sa, const void* g, bool ok) {
    int sz = ok ? 16 : 0;
    asm volatile("cp.async.cg.shared.global [%0], [%1], 16, %2;"
                 :: "r"(sa), "l"(g), "r"(sz) : "memory");
}
#define CP_COMMIT() asm volatile("cp.async.commit_group;" ::: "memory")
#define CP_WAIT(n)  asm volatile("cp.async.wait_group %0;" :: "n"(n) : "memory")

__device__ __forceinline__ void ldsm4(uint32_t* r, uint32_t addr) {
    asm volatile("ldmatrix.sync.aligned.m8n8.x4.shared.b16 {%0,%1,%2,%3}, [%4];"
                 : "=r"(r[0]), "=r"(r[1]), "=r"(r[2]), "=r"(r[3]) : "r"(addr));
}
__device__ __forceinline__ void mma_bf16(float* c, const uint32_t* a, const uint32_t* b) {
    asm volatile(
        "mma.sync.aligned.m16n8k16.row.col.f32.bf16.bf16.f32 "
        "{%0,%1,%2,%3}, {%4,%5,%6,%7}, {%8,%9}, {%0,%1,%2,%3};"
        : "+f"(c[0]), "+f"(c[1]), "+f"(c[2]), "+f"(c[3])
        : "r"(a[0]), "r"(a[1]), "r"(a[2]), "r"(a[3]), "r"(b[0]), "r"(b[1]));
}

// ---------------------------------------------------------------------------
// Fused prep kernel: transpose + all 4 weight reorders.
// ---------------------------------------------------------------------------
__device__ void wb_region(const float* __restrict__ W, __nv_bfloat16* __restrict__ Wb,
                          int CINR, int CINP, int COUTR, int COUTP,
                          size_t tidg, size_t nthreads) {
    int K = CINP * 9;
    size_t total = (size_t)8 * COUTP * K;
    for (size_t i = tidg; i < total; i += nthreads) {
        int k = (int)(i % K);
        size_t rem = i / K;
        int m = (int)(rem % COUTP);
        int g = (int)(rem / COUTP);
        int tap = k / CINP, cin = k - tap * CINP;
        float v = 0.f;
        if (m < COUTR && cin < CINR)
            v = W[((size_t)(g * COUTR + m) * CINR + cin) * 9 + tap];
        Wb[i] = __float2bfloat16_rn(v);
    }
}

__global__ __launch_bounds__(256)
void prep_all(const float* __restrict__ gar, const float* __restrict__ cond,
              __nv_bfloat16* __restrict__ inTb, __half* __restrict__ garTh,
              const float* __restrict__ W1, __nv_bfloat16* __restrict__ wb1,
              const float* __restrict__ W2, __nv_bfloat16* __restrict__ wb2,
              const float* __restrict__ W3, __nv_bfloat16* __restrict__ wb3,
              const float* __restrict__ W4, __nv_bfloat16* __restrict__ wb4) {
    if (blockIdx.x < 2048) {
        __shared__ float tile[32][33];
        int tx = threadIdx.x & 31;
        int ty = threadIdx.x >> 5;
        int p0 = (blockIdx.x & 127) * 32;
        int c0 = (blockIdx.x >> 7) * 32;
        for (int i = ty; i < 32; i += 8) {
            int c = c0 + i;
            const float* src = (c < 256) ? (gar + (size_t)c * NP)
                                         : (cond + (size_t)(c - 256) * NP);
            tile[i][tx] = src[p0 + tx];
        }
        __syncthreads();
        for (int i = ty; i < 32; i += 8) {
            float v = tile[tx][i];
            int pix = p0 + i, c = c0 + tx;
            inTb[(size_t)pix * 512 + c] = __float2bfloat16_rn(v);
            if (c0 < 256)
                garTh[(size_t)pix * 256 + c] = __float2half_rn(v);
        }
    } else {
        size_t tidg = (size_t)(blockIdx.x - 2048) * 256 + threadIdx.x;
        size_t nt   = (size_t)2752 * 256;
        wb_region(W1, wb1, 512, 512, 128, 128, tidg, nt);
        wb_region(W2, wb2, 128, 128,  64,  64, tidg, nt);
        wb_region(W3, wb3,  64,  64,  32,  32, tidg, nt);
        wb_region(W4, wb4,  32,  64,  18,  32, tidg, nt);
    }
}

// ---------------------------------------------------------------------------
// bf16 band-reuse implicit-GEMM 3x3 conv. 128 threads (4 warps, 64x64 tiles).
//   NCC==1 (CIN=64): single band + ALL 9 B tap-chunks preloaded, zero in-loop
//   barriers, 3 CTAs/SM. Otherwise: double-buffered band + B, ONE barrier per
//   tap-chunk, next chunk's cp.async overlaps current chunk's MMAs.
// ---------------------------------------------------------------------------
template<int CIN, int COUT, int COUT_REAL, int OUT_STRIDE, bool RELU, int OUT_MODE, int MINB>
__global__ __launch_bounds__(128, MINB)
void mconv(const __nv_bfloat16* __restrict__ in, size_t gstride,
           const __nv_bfloat16* __restrict__ Wb, const float* __restrict__ bias,
           void* __restrict__ outv) {
    constexpr int  K       = CIN * 9;
    constexpr int  NCC     = CIN / 64;
    constexpr int  TOT     = NCC * 9;
    constexpr bool PRELOAD = (NCC == 1);
    constexpr int  WN      = COUT / 2;
    constexpr int  NTT     = WN / 8;
    constexpr int  BPIX    = 264;              // 4 rows x 66 cols
    constexpr int  BSTAGE  = BPIX * 128;       // band stage bytes
    constexpr int  BBS     = COUT * 128;       // B stage bytes
    constexpr int  NBAND   = PRELOAD ? 1 : 2;

    extern __shared__ char sm[];
    uint32_t dyn  = smem_u32(sm);
    uint32_t base = (dyn + 1023u) & ~1023u;

    const int tid  = threadIdx.x;
    const int warp = tid >> 5;
    const int lane = tid & 31;
    const int lq   = lane >> 2;
    const int lc   = lane & 3;
    const int wm   = warp & 1;
    const int wn   = warp >> 1;
    const int tile = blockIdx.x;
    const int g    = blockIdx.y;
    const int y0   = tile * 2 - 1;

    const __nv_bfloat16* src = in + (size_t)g * gstride;
    const __nv_bfloat16* wg  = Wb + (size_t)g * COUT * K;

    const uint32_t bandBase = base;
    const uint32_t bbBase   = base + NBAND * BSTAGE;

    float acc[4][NTT][4];
    #pragma unroll
    for (int i = 0; i < 4; i++)
        #pragma unroll
        for (int j = 0; j < NTT; j++)
            #pragma unroll
            for (int q = 0; q < 4; q++) acc[i][j][q] = 0.f;

    auto band_load = [&](int cc, int buf) {
        int c0 = cc * 64;
        for (int it = tid; it < BPIX * 8; it += 128) {
            int bp = it >> 3, seg = it & 7;
            int br = bp / 66;
            int col = bp - br * 66;
            int y = y0 + br, x = col - 1;
            bool ok = ((unsigned)y < 64u) & ((unsigned)x < 64u);
            int pix = ok ? (y * 64 + x) : 0;
            const __nv_bfloat16* gp = src + (size_t)pix * CIN + c0 + seg * 8;
            cp16(bandBase + buf * BSTAGE
                 + (uint32_t)(bp * 128 + ((seg * 16) ^ ((bp & 7) * 16))), gp, ok);
        }
    };
    auto b_load = [&](int kc, int stage) {
        int cc = kc / 9;
        int koff = (kc - cc * 9) * CIN + cc * 64;
        for (int it = tid; it < COUT * 8; it += 128) {
            int m = it >> 3, seg = it & 7;
            const __nv_bfloat16* gp = wg + (size_t)m * K + koff + seg * 8;
            cp16(bbBase + stage * BBS
                 + (uint32_t)(m * 128 + ((seg * 16) ^ ((m & 7) * 16))), gp, true);
        }
    };

    // lane-constant ldmatrix address components (A fragments)
    const int amat  = lane >> 3;
    const int aroff = (lane & 7) + (amat & 1) * 8;
    const int akb   = (amat >> 1) * 16;

    auto compute = [&](int tap, int bandbuf, int bstage) {
        int r = tap / 3, s = tap - 3 * (tap / 3);
        int bbase0 = (wm + r) * 66 + s;
        uint32_t aS = bandBase + bandbuf * BSTAGE;
        uint32_t bS = bbBase + bstage * BBS;
        #pragma unroll
        for (int seg = 0; seg < 4; seg++) {
            uint32_t af[4][4];
            #pragma unroll
            for (int mt = 0; mt < 4; mt++) {
                int bp = bbase0 + mt * 16 + aroff;
                uint32_t addr = aS + (uint32_t)(bp * 128 + ((seg * 32 + akb) ^ ((bp & 7) * 16)));
                ldsm4(af[mt], addr);
            }
            uint32_t bf[NTT][2];
            #pragma unroll
            for (int ntp = 0; ntp < NTT / 2; ntp++) {
                int n = wn * WN + (ntp * 2 + (lane >> 4)) * 8 + (lane & 7);
                int kb = ((lane >> 3) & 1) * 16;
                uint32_t addr = bS + (uint32_t)(n * 128 + ((seg * 32 + kb) ^ ((n & 7) * 16)));
                uint32_t tmp[4];
                ldsm4(tmp, addr);
                bf[2 * ntp][0] = tmp[0]; bf[2 * ntp][1] = tmp[1];
                bf[2 * ntp + 1][0] = tmp[2]; bf[2 * ntp + 1][1] = tmp[3];
            }
            #pragma unroll
            for (int mt = 0; mt < 4; mt++)
                #pragma unroll
                for (int nt = 0; nt < NTT; nt++)
                    mma_bf16(acc[mt][nt], af[mt], bf[nt]);
        }
    };

    if (PRELOAD) {
        // Single band + all 9 B tap-chunks; zero in-loop barriers.
        band_load(0, 0);
        #pragma unroll
        for (int t9 = 0; t9 < 9; t9++) b_load(t9, t9);
        CP_COMMIT();
        CP_WAIT(0);
        __syncthreads();
        #pragma unroll
        for (int tap = 0; tap < 9; tap++)
            compute(tap, 0, tap);
    } else {
        band_load(0, 0); b_load(0, 0); CP_COMMIT();
        for (int kc = 0; kc < TOT; kc++) {
            CP_WAIT(0);
            __syncthreads();                  // all threads past compute(kc-1)
            int nb = kc + 1;
            if (nb < TOT) {                   // issue next loads, overlap compute
                if (nb % 9 == 0) band_load(nb / 9, (nb / 9) & 1);
                b_load(nb, nb & 1);
                CP_COMMIT();
            }
            int cc = kc / 9, tap = kc - cc * 9;
            compute(tap, cc & 1, kc & 1);
        }
    }

    // Epilogue: bias + lrelu, store.
    #pragma unroll
    for (int mt = 0; mt < 4; mt++) {
        int prow = tile * 128 + wm * 64 + mt * 16 + lq;
        #pragma unroll
        for (int nt = 0; nt < NTT; nt++) {
            int n0 = wn * WN + nt * 8 + lc * 2;
            float b0 = (n0     < COUT_REAL) ? bias[g * COUT_REAL + n0]     : 0.f;
            float b1 = (n0 + 1 < COUT_REAL) ? bias[g * COUT_REAL + n0 + 1] : 0.f;
            #pragma unroll
            for (int h = 0; h < 2; h++) {
                int p = prow + h * 8;
                float v0 = acc[mt][nt][h * 2]     + b0;
                float v1 = acc[mt][nt][h * 2 + 1] + b1;
                if (RELU) {
                    v0 = (v0 >= 0.f) ? v0 : 0.1f * v0;
                    v1 = (v1 >= 0.f) ? v1 : 0.1f * v1;
                }
                if (OUT_MODE == 0) {
                    __nv_bfloat16* ob = (__nv_bfloat16*)outv;
                    __nv_bfloat162 pr;
                    pr.x = __float2bfloat16_rn(v0);
                    pr.y = __float2bfloat16_rn(v1);
                    *(__nv_bfloat162*)(ob + ((size_t)g * NP + p) * OUT_STRIDE + n0) = pr;
                } else {
                    float* of = (float*)outv;
                    if (n0 < COUT_REAL)
                        of[(size_t)(g * COUT_REAL + n0) * NP + p] = v0;
                    if (n0 + 1 < COUT_REAL)
                        of[(size_t)(g * COUT_REAL + n0 + 1) * NP + p] = v1;
                }
            }
        }
    }
}

// ---------------------------------------------------------------------------
// Final warp/sample kernel with tap dedup.
//   Phase 1 (24 thr): softmax + bilinear taps (attn folded) per (pixel,k).
//   Phase 2 (32 thr): merge each (pixel,group)'s 24 taps by integer position
//                     into a compact list (exact; fp32 add reorder only).
//   Phase 3 (256 thr = channels): gather compact lists from garTh [4096][256].
// ---------------------------------------------------------------------------
__global__ __launch_bounds__(256)
void warp_kernel(const float* __restrict__ oa, const __half* __restrict__ garTh,
                 const float* __restrict__ mask, float* __restrict__ out) {
    __shared__ int   sO[4][192];
    __shared__ float sA[4][192];
    __shared__ int   sPosC[4][8][24];
    __shared__ float sWC[4][8][24];
    __shared__ int   sCnt[4][8];

    const int pix0 = blockIdx.x * 4;
    const int tt = threadIdx.x;

    if (tt < 24) {
        int p = tt / 6, k = tt - (tt / 6) * 6;
        int pix = pix0 + p;
        float fx = (float)(pix & 63);
        float fy = (float)(pix >> 6);
        float lg[8], ox[8], oy[8];
        #pragma unroll
        for (int g = 0; g < 8; g++) {
            const float* base = oa + (size_t)g * 18 * NP + pix;
            lg[g] = base[(12 + k) * NP];
            ox[g] = base[(2 * k) * NP];
            oy[g] = base[(2 * k + 1) * NP];
        }
        float m = lg[0];
        #pragma unroll
        for (int g = 1; g < 8; g++) m = fmaxf(m, lg[g]);
        float s = 0.f;
        #pragma unroll
        for (int g = 0; g < 8; g++) { lg[g] = expf(lg[g] - m); s += lg[g]; }
        float inv = 1.f / s;
        #pragma unroll
        for (int g = 0; g < 8; g++) {
            float attn = lg[g] * inv;
            float xs = fminf(fmaxf((fx + ox[g]) * (64.0f / 63.0f) - 0.5f, 0.f), 63.f);
            float ys = fminf(fmaxf((fy + oy[g]) * (64.0f / 63.0f) - 0.5f, 0.f), 63.f);
            float x0f = floorf(xs), y0f = floorf(ys);
            float wx = xs - x0f, wy = ys - y0f;
            int x0 = (int)x0f, y0 = (int)y0f;
            int x1 = min(x0 + 1, 63), y1 = min(y0 + 1, 63);
            int q = (p * 6 + k) * 8 + g;
            sO[0][q] = (y0 * 64 + x0) * 256;
            sO[1][q] = (y0 * 64 + x1) * 256;
            sO[2][q] = (y1 * 64 + x0) * 256;
            sO[3][q] = (y1 * 64 + x1) * 256;
            sA[0][q] = attn * (1.f - wy) * (1.f - wx);
            sA[1][q] = attn * (1.f - wy) * wx;
            sA[2][q] = attn * wy * (1.f - wx);
            sA[3][q] = attn * wy * wx;
        }
    }
    __syncthreads();

    if (tt < 32) {
        int p = tt >> 3, g = tt & 7;
        int cnt = 0;
        for (int k = 0; k < 6; k++) {
            int qbase = (p * 6 + k) * 8 + g;
            #pragma unroll
            for (int q = 0; q < 4; q++) {
                int   po = sO[q][qbase];
                float ww = sA[q][qbase];
                int j = 0;
                for (; j < cnt; j++) {
                    if (sPosC[p][g][j] == po) { sWC[p][g][j] += ww; break; }
                }
                if (j == cnt) { sPosC[p][g][cnt] = po; sWC[p][g][cnt] = ww; cnt++; }
            }
        }
        sCnt[p][g] = cnt;
    }
    __syncthreads();

    const int c = tt;  // channel
    float mk[8];
    #pragma unroll
    for (int g = 0; g < 8; g++) mk[g] = mask[g * 256 + c];

    for (int p = 0; p < 4; p++) {
        float accP = 0.f;
        #pragma unroll
        for (int g = 0; g < 8; g++) {
            int cnt = sCnt[p][g];      // uniform across block
            float accG = 0.f;
            for (int j = 0; j < cnt; j++)
                accG += sWC[p][g][j] * __half2float(garTh[sPosC[p][g][j] + c]);
            accP += accG * mk[g];
        }
        out[(size_t)c * NP + pix0 + p] = accP;
    }
}

// ---------------------------------------------------------------------------
extern "C" void kernel_launch(void* const* d_in, const int* in_sizes, int n_in,
                              void* d_out, int out_size) {
    const float* gar  = (const float*)d_in[0];
    const float* cond = (const float*)d_in[1];
    const float* mask = (const float*)d_in[2];
    const float* W1   = (const float*)d_in[3];
    const float* b1   = (const float*)d_in[4];
    const float* W2   = (const float*)d_in[5];
    const float* b2   = (const float*)d_in[6];
    const float* W3   = (const float*)d_in[7];
    const float* b3   = (const float*)d_in[8];
    const float* W4   = (const float*)d_in[9];
    const float* b4   = (const float*)d_in[10];
    float* out = (float*)d_out;

    float* S = nullptr;
    cudaGetSymbolAddress((void**)&S, g_scratch);
    __nv_bfloat16* inTb  = (__nv_bfloat16*)(S + OFF_INT);
    __half*        garTh = (__half*)       (S + OFF_GART);
    __nv_bfloat16* wb1   = (__nv_bfloat16*)(S + OFF_WB1);
    __nv_bfloat16* wb2   = (__nv_bfloat16*)(S + OFF_WB2);
    __nv_bfloat16* wb3   = (__nv_bfloat16*)(S + OFF_WB3);
    __nv_bfloat16* wb4   = (__nv_bfloat16*)(S + OFF_WB4);
    __nv_bfloat16* h1    = (__nv_bfloat16*)(S + OFF_H1);
    __nv_bfloat16* h2    = (__nv_bfloat16*)(S + OFF_H2);
    __nv_bfloat16* h3    = (__nv_bfloat16*)(S + OFF_H3);
    float*         oa    = S + OFF_OA;

    // dynamic smem
    const int SM1  = 2 * 264 * 128 + 2 * 128 * 128 + 1024;  // 101376
    const int SM2  = 2 * 264 * 128 + 2 * 64 * 128 + 1024;   //  84992
    const int SM34 = 1 * 264 * 128 + 9 * 32 * 128 + 1024;   //  71680

    cudaFuncSetAttribute(mconv<512,128,128,128,true ,0,2>, cudaFuncAttributeMaxDynamicSharedMemorySize, SM1);
    cudaFuncSetAttribute(mconv<128, 64, 64, 64,true ,0,2>, cudaFuncAttributeMaxDynamicSharedMemorySize, SM2);
    cudaFuncSetAttribute(mconv< 64, 32, 32, 64,true ,0,3>, cudaFuncAttributeMaxDynamicSharedMemorySize, SM34);
    cudaFuncSetAttribute(mconv< 64, 32, 18,  1,false,1,3>, cudaFuncAttributeMaxDynamicSharedMemorySize, SM34);

    prep_all<<<2048 + 2752, 256>>>(gar, cond, inTb, garTh,
                                   W1, wb1, W2, wb2, W3, wb3, W4, wb4);

    mconv<512,128,128,128,true ,0,2><<<dim3(32, 8), 128, SM1 >>>(inTb, 0,               wb1, b1, h1);
    mconv<128, 64, 64, 64,true ,0,2><<<dim3(32, 8), 128, SM2 >>>(h1, (size_t)NP * 128,  wb2, b2, h2);
    mconv< 64, 32, 32, 64,true ,0,3><<<dim3(32, 8), 128, SM34>>>(h2, (size_t)NP * 64,   wb3, b3, h3);
    mconv< 64, 32, 18,  1,false,1,3><<<dim3(32, 8), 128, SM34>>>(h3, (size_t)NP * 64,   wb4, b4, oa);

    warp_kernel<<<NP / 4, 256>>>(oa, garTh, mask, out);
}